// round 5
// baseline (speedup 1.0000x reference)
#include <cuda_runtime.h>
#include <cuda_bf16.h>
#include <cstdint>

// ===========================================================================
// TGNN — fused bf16 mma.sync trunk.
//   fused_embed_p1 : pairs -> h384 (smem only) -> h512 (gmem bf16)
//   fused_p2_segsum: h512 -> h256 (smem only) -> deterministic segment sums
//   hm_combine     : merge 2-slot partials, divide by counts -> hm fp32
//   batch (B=2000): p3, f1 tf32 mma; f2/final SIMT fp32
// ===========================================================================

#define P_MAX  200000
#define B_MAX  2000

__device__ __nv_bfloat16 g_pairs_bf[(size_t)P_MAX * 160];
__device__ __nv_bfloat16 g_h512[(size_t)P_MAX * 512];
__device__ float g_part[2 * (size_t)B_MAX * 256];
__device__ float g_hm  [(size_t)B_MAX * 256];
__device__ float g_y   [(size_t)B_MAX * 1024];
__device__ float g_z   [(size_t)B_MAX * 512];
__device__ float g_w   [(size_t)B_MAX * 32];
__device__ __nv_bfloat16 g_wbf[1024 * 1024];
__device__ float g_wtf [1024 * 1024];

// ---------------------------------------------------------------------------
__device__ __forceinline__ float tf32_round(float x) {
    uint32_t r;
    asm("cvt.rna.tf32.f32 %0, %1;" : "=r"(r) : "f"(x));
    return __uint_as_float(r);
}
__device__ __forceinline__ uint32_t tf32_round_bits(float x) {
    uint32_t r;
    asm("cvt.rna.tf32.f32 %0, %1;" : "=r"(r) : "f"(x));
    return r;
}
__device__ __forceinline__ void cp_async16(uint32_t smem_addr, const void* gptr, int src_bytes) {
    asm volatile("cp.async.ca.shared.global [%0], [%1], 16, %2;\n"
                 :: "r"(smem_addr), "l"(gptr), "r"(src_bytes));
}
#define CP_ASYNC_COMMIT() asm volatile("cp.async.commit_group;\n" ::: "memory")
#define CP_ASYNC_WAIT0()  asm volatile("cp.async.wait_group 0;\n" ::: "memory")

__device__ __forceinline__ uint32_t smem_u32(const void* p) {
    uint32_t a;
    asm("{ .reg .u64 t; cvta.to.shared.u64 t, %1; cvt.u32.u64 %0, t; }" : "=r"(a) : "l"(p));
    return a;
}
__device__ __forceinline__ void mma_bf16(float& c0, float& c1, float& c2, float& c3,
                                         uint32_t a0, uint32_t a1, uint32_t a2, uint32_t a3,
                                         uint32_t b0, uint32_t b1) {
    asm volatile(
        "mma.sync.aligned.m16n8k16.row.col.f32.bf16.bf16.f32 "
        "{%0,%1,%2,%3}, {%4,%5,%6,%7}, {%8,%9}, {%0,%1,%2,%3};"
        : "+f"(c0), "+f"(c1), "+f"(c2), "+f"(c3)
        : "r"(a0), "r"(a1), "r"(a2), "r"(a3), "r"(b0), "r"(b1));
}
__device__ __forceinline__ void mma_tf32(float& c0, float& c1, float& c2, float& c3,
                                         uint32_t a0, uint32_t a1, uint32_t a2, uint32_t a3,
                                         uint32_t b0, uint32_t b1) {
    asm volatile(
        "mma.sync.aligned.m16n8k8.row.col.f32.tf32.tf32.f32 "
        "{%0,%1,%2,%3}, {%4,%5,%6,%7}, {%8,%9}, {%0,%1,%2,%3};"
        : "+f"(c0), "+f"(c1), "+f"(c2), "+f"(c3)
        : "r"(a0), "r"(a1), "r"(a2), "r"(a3), "r"(b0), "r"(b1));
}

// ---------------------------------------------------------------------------
// Shared bf16 GEMM building blocks.
//   Tile block = 128 rows x 32 k, bf16, smem row = 64B data + 16B pad (80B).
//   Fragment banks: word = 20g + t (mod 32) — all 32 distinct.
// ---------------------------------------------------------------------------
#define TILE_B 10240

__device__ __forceinline__ void load_tile(uint32_t dst, const __nv_bfloat16* __restrict__ src,
                                          int ld, int rbase, int rmax, int k0, int tid)
{
#pragma unroll
    for (int h = 0; h < 2; h++) {
        const int chunk = tid + h * 256;        // 0..511
        const int row = chunk >> 2;
        const int ck  = chunk & 3;
        const int gr  = rbase + row;
        const char* p = (const char*)(src + (size_t)gr * ld + k0 + ck * 8);
        cp_async16(dst + row * 80 + ck * 16, p, gr < rmax ? 16 : 0);
    }
}

__device__ __forceinline__ void mma_block(const uint32_t* __restrict__ Aw,
                                          const uint32_t* __restrict__ Bw,
                                          float acc[2][8][4],
                                          int g, int t, int warp_m, int warp_n)
{
#pragma unroll
    for (int ks = 0; ks < 2; ks++) {
        const int kw = ks * 8 + t;
        uint32_t a[2][4];
#pragma unroll
        for (int mt = 0; mt < 2; mt++) {
            const int m0 = warp_m + mt * 16 + g;
            a[mt][0] = Aw[m0 * 20 + kw];
            a[mt][1] = Aw[(m0 + 8) * 20 + kw];
            a[mt][2] = Aw[m0 * 20 + kw + 4];
            a[mt][3] = Aw[(m0 + 8) * 20 + kw + 4];
        }
        uint32_t b[8][2];
#pragma unroll
        for (int nt = 0; nt < 8; nt++) {
            const int n0 = warp_n + nt * 8 + g;
            b[nt][0] = Bw[n0 * 20 + kw];
            b[nt][1] = Bw[n0 * 20 + kw + 4];
        }
#pragma unroll
        for (int mt = 0; mt < 2; mt++)
#pragma unroll
            for (int nt = 0; nt < 8; nt++)
                mma_bf16(acc[mt][nt][0], acc[mt][nt][1], acc[mt][nt][2], acc[mt][nt][3],
                         a[mt][0], a[mt][1], a[mt][2], a[mt][3],
                         b[nt][0], b[nt][1]);
    }
}

// ===========================================================================
// fused_embed_p1: per CTA 128 rows.
//   smem: [0, 122880)  h384 tile, 12 k-blocks of TILE_B
//         [122880, +2*TILE_B)  stage pair 0 (A in ph1, B in ph2)
//         [143360, +2*TILE_B)  stage pair 1 (B in ph1)
// ===========================================================================
#define SMEM_EP1 (12 * TILE_B + 4 * TILE_B)    // 163840

__global__ __launch_bounds__(256)
void fused_embed_p1(const __nv_bfloat16* __restrict__ pairs,
                    const __nv_bfloat16* __restrict__ awt,
                    const __nv_bfloat16* __restrict__ bwt,
                    const float* __restrict__ ab, const float* __restrict__ bb,
                    const __nv_bfloat16* __restrict__ p1t,
                    const float* __restrict__ p1b,
                    __nv_bfloat16* __restrict__ h512, int P)
{
    extern __shared__ char smem[];
    const uint32_t smem_base = smem_u32(smem);
    const uint32_t stA = smem_base + 122880;
    const uint32_t stB = smem_base + 143360;

    const int tid = threadIdx.x;
    const int wid = tid >> 5, lane = tid & 31;
    const int g = lane >> 2, t = lane & 3;
    const int warp_m = (wid & 3) * 32;
    const int warp_n = (wid >> 2) * 64;
    const int blockRow = blockIdx.x * 128;

    float acc[2][8][4];

    // ---------------- phase 1: embed -> h384 (smem) ----------------
    for (int c = 0; c < 3; c++) {
        const __nv_bfloat16* Ap = pairs + (c == 0 ? 0 : c == 1 ? 64 : 128);
        const __nv_bfloat16* Wc = (c < 2) ? awt : bwt;
        const float* biasc = (c < 2) ? ab : bb;
        const int Kc = (c < 2) ? 64 : 32;
        const int NIT = Kc >> 5;

#pragma unroll
        for (int mt = 0; mt < 2; mt++)
#pragma unroll
            for (int nt = 0; nt < 8; nt++)
#pragma unroll
                for (int i = 0; i < 4; i++) acc[mt][nt][i] = 0.0f;

        load_tile(stA, Ap, 160, blockRow, P, 0, tid);
        load_tile(stB, Wc, Kc, 0, 1 << 30, 0, tid);
        CP_ASYNC_COMMIT();

        for (int it = 0; it < NIT; it++) {
            CP_ASYNC_WAIT0();
            __syncthreads();
            if (it + 1 < NIT) {
                load_tile(stA + TILE_B, Ap, 160, blockRow, P, 32, tid);
                load_tile(stB + TILE_B, Wc, Kc, 0, 1 << 30, 32, tid);
                CP_ASYNC_COMMIT();
            }
            mma_block((const uint32_t*)(smem + 122880 + (it & 1) * TILE_B),
                      (const uint32_t*)(smem + 143360 + (it & 1) * TILE_B),
                      acc, g, t, warp_m, warp_n);
            __syncthreads();
        }
        // epilogue -> h384 smem (BROW layout)
#pragma unroll
        for (int nt = 0; nt < 8; nt++) {
            const int col = warp_n + nt * 8 + 2 * t;
            const float2 bv = *(const float2*)&biasc[col];
            const int gc = c * 128 + col;
            const int kb = gc >> 5;
            const int kin = gc & 31;
#pragma unroll
            for (int mt = 0; mt < 2; mt++)
#pragma unroll
                for (int half = 0; half < 2; half++) {
                    const int row = warp_m + mt * 16 + half * 8 + g;
                    float v0 = fmaxf(acc[mt][nt][half * 2 + 0] + bv.x, 0.f);
                    float v1 = fmaxf(acc[mt][nt][half * 2 + 1] + bv.y, 0.f);
                    *(__nv_bfloat162*)(smem + kb * TILE_B + row * 80 + kin * 2) =
                        __float22bfloat162_rn(make_float2(v0, v1));
                }
        }
    }
    __syncthreads();   // h384 complete, visible to all

    // ---------------- phase 2: p1 (A from smem, B streamed) ----------------
    for (int nc = 0; nc < 4; nc++) {
#pragma unroll
        for (int mt = 0; mt < 2; mt++)
#pragma unroll
            for (int nt = 0; nt < 8; nt++)
#pragma unroll
                for (int i = 0; i < 4; i++) acc[mt][nt][i] = 0.0f;

        load_tile(stA, p1t, 384, nc * 128, 1 << 30, 0, tid);
        CP_ASYNC_COMMIT();

        for (int kb = 0; kb < 12; kb++) {
            CP_ASYNC_WAIT0();
            __syncthreads();
            if (kb + 1 < 12) {
                load_tile(stA + ((kb + 1) & 1) * TILE_B, p1t, 384, nc * 128, 1 << 30,
                          (kb + 1) * 32, tid);
                CP_ASYNC_COMMIT();
            }
            mma_block((const uint32_t*)(smem + kb * TILE_B),
                      (const uint32_t*)(smem + 122880 + (kb & 1) * TILE_B),
                      acc, g, t, warp_m, warp_n);
            __syncthreads();
        }
        // epilogue -> h512 gmem bf16
#pragma unroll
        for (int nt = 0; nt < 8; nt++) {
            const int col = nc * 128 + warp_n + nt * 8 + 2 * t;
            const float2 bv = *(const float2*)&p1b[col];
#pragma unroll
            for (int mt = 0; mt < 2; mt++)
#pragma unroll
                for (int half = 0; half < 2; half++) {
                    const int row = blockRow + warp_m + mt * 16 + half * 8 + g;
                    if (row >= P) continue;
                    float v0 = fmaxf(acc[mt][nt][half * 2 + 0] + bv.x, 0.f);
                    float v1 = fmaxf(acc[mt][nt][half * 2 + 1] + bv.y, 0.f);
                    *(__nv_bfloat162*)(h512 + (size_t)row * 512 + col) =
                        __float22bfloat162_rn(make_float2(v0, v1));
                }
        }
    }
}

// ===========================================================================
// fused_p2_segsum: p2 GEMM + in-CTA segment reduction.
//   smem: [0, 2*TILE_B) A stages; [20480, +2*TILE_B) B stages;
//         [40960, +128*129*4) fp32 reduction tile (stride 129: conflict-free
//         column reads).
//   Each segment spans <=2 CTAs; partial sums go to part[slot][seg][col] with
//   <=2 atomicAdds per location -> bitwise deterministic.
// ===========================================================================
#define REDPAD 129
#define SMEM_P2 (4 * TILE_B + 128 * REDPAD * 4)   // 107008

__global__ __launch_bounds__(256)
void fused_p2_segsum(const __nv_bfloat16* __restrict__ h512,
                     const __nv_bfloat16* __restrict__ p2t,
                     const float* __restrict__ p2b,
                     float* __restrict__ part, int P, int group, int Bseg)
{
    extern __shared__ char smem[];
    const uint32_t smem_base = smem_u32(smem);
    const uint32_t stA = smem_base;
    const uint32_t stB = smem_base + 2 * TILE_B;
    float* red = (float*)(smem + 4 * TILE_B);

    const int tid = threadIdx.x;
    const int wid = tid >> 5, lane = tid & 31;
    const int g = lane >> 2, t = lane & 3;
    const int warp_m = (wid & 3) * 32;
    const int warp_n = (wid >> 2) * 64;
    const int blockRow = blockIdx.x * 128;

    float acc[2][8][4];

    for (int nc = 0; nc < 2; nc++) {
#pragma unroll
        for (int mt = 0; mt < 2; mt++)
#pragma unroll
            for (int nt = 0; nt < 8; nt++)
#pragma unroll
                for (int i = 0; i < 4; i++) acc[mt][nt][i] = 0.0f;

        load_tile(stA, h512, 512, blockRow, P, 0, tid);
        load_tile(stB, p2t, 512, nc * 128, 1 << 30, 0, tid);
        CP_ASYNC_COMMIT();

        for (int kb = 0; kb < 16; kb++) {
            CP_ASYNC_WAIT0();
            __syncthreads();
            if (kb + 1 < 16) {
                load_tile(stA + ((kb + 1) & 1) * TILE_B, h512, 512, blockRow, P,
                          (kb + 1) * 32, tid);
                load_tile(stB + ((kb + 1) & 1) * TILE_B, p2t, 512, nc * 128, 1 << 30,
                          (kb + 1) * 32, tid);
                CP_ASYNC_COMMIT();
            }
            mma_block((const uint32_t*)(smem + (kb & 1) * TILE_B),
                      (const uint32_t*)(smem + 2 * TILE_B + (kb & 1) * TILE_B),
                      acc, g, t, warp_m, warp_n);
            __syncthreads();
        }
        // epilogue -> fp32 red tile
#pragma unroll
        for (int nt = 0; nt < 8; nt++) {
            const int col = warp_n + nt * 8 + 2 * t;
            const float2 bv = *(const float2*)&p2b[nc * 128 + col];
#pragma unroll
            for (int mt = 0; mt < 2; mt++)
#pragma unroll
                for (int half = 0; half < 2; half++) {
                    const int row = warp_m + mt * 16 + half * 8 + g;
                    red[row * REDPAD + col]     = fmaxf(acc[mt][nt][half * 2 + 0] + bv.x, 0.f);
                    red[row * REDPAD + col + 1] = fmaxf(acc[mt][nt][half * 2 + 1] + bv.y, 0.f);
                }
        }
        __syncthreads();

        // segment reduction: thread = (col, row-half)
        {
            const int col = tid & 127;
            const int rb  = (tid >> 7) * 64;
            float s = 0.f;
            bool any = false;
            int curseg = 0, nxt = 0;
            for (int r = rb; r < rb + 64; r++) {
                const int grow = blockRow + r;
                if (grow >= P) break;
                if (!any) {
                    curseg = grow / group;
                    nxt = (curseg + 1) * group;
                    any = true;
                } else if (grow >= nxt) {
                    const int slot = blockIdx.x - (curseg * group) / 128;
                    atomicAdd(&part[(size_t)slot * Bseg * 256 + curseg * 256 + nc * 128 + col], s);
                    s = 0.f;
                    curseg++;
                    nxt += group;
                }
                s += red[r * REDPAD + col];
            }
            if (any) {
                const int slot = blockIdx.x - (curseg * group) / 128;
                atomicAdd(&part[(size_t)slot * Bseg * 256 + curseg * 256 + nc * 128 + col], s);
            }
        }
        __syncthreads();
    }
}

// ---------------------------------------------------------------------------
__global__ void zero_kernel(float* __restrict__ p, int n)
{
    int i = blockIdx.x * blockDim.x + threadIdx.x;
    if (i < n) p[i] = 0.0f;
}

__global__ void hm_combine(const float* __restrict__ part, const int* __restrict__ idx,
                           float* __restrict__ hm, int Bseg)
{
    int i = blockIdx.x * blockDim.x + threadIdx.x;
    if (i >= Bseg * 256) return;
    int s = i >> 8;
    hm[i] = (part[i] + part[(size_t)Bseg * 256 + i]) / (float)idx[s];
}

// ---------------------------------------------------------------------------
// conversions
// ---------------------------------------------------------------------------
__global__ void cvt_f32_bf16(const float* __restrict__ src,
                             __nv_bfloat16* __restrict__ dst, int n2)
{
    int i = blockIdx.x * blockDim.x + threadIdx.x;
    if (i >= n2) return;
    float2 v = reinterpret_cast<const float2*>(src)[i];
    reinterpret_cast<__nv_bfloat162*>(dst)[i] = __float22bfloat162_rn(v);
}

// out[n*K + k] = bf16(in[k*N + n])
__global__ void wt_bf16(const float* __restrict__ in,
                        __nv_bfloat16* __restrict__ out, int K, int N)
{
    int i = blockIdx.x * blockDim.x + threadIdx.x;
    if (i >= K * N) return;
    int n = i / K, k = i % K;
    out[i] = __float2bfloat16(in[(size_t)k * N + n]);
}

__global__ void round_copy(const float* __restrict__ src, float* __restrict__ dst, int n4)
{
    int i = blockIdx.x * blockDim.x + threadIdx.x;
    if (i >= n4) return;
    float4 v = reinterpret_cast<const float4*>(src)[i];
    v.x = tf32_round(v.x); v.y = tf32_round(v.y);
    v.z = tf32_round(v.z); v.w = tf32_round(v.w);
    reinterpret_cast<float4*>(dst)[i] = v;
}

// ===========================================================================
// tf32 tensor GEMM (proven) — batch layers p3, f1
// ===========================================================================
#define ASTRIDE 20
#define BSTRIDE 136
#define ASZ (128 * ASTRIDE * 4)
#define BSZ (16 * BSTRIDE * 4)
#define STG (ASZ + BSZ)
#define SMEM_TF (2 * STG)

__global__ __launch_bounds__(256)
void tc_gemm_tf32(const float* __restrict__ A, int lda,
                  const float* __restrict__ W,
                  const float* __restrict__ bias,
                  float* __restrict__ C, int ldc,
                  int M, int N, int K, int relu)
{
    __shared__ __align__(16) char smem[SMEM_TF];
    const uint32_t smem_base = smem_u32(smem);

    const int tid  = threadIdx.x;
    const int wid  = tid >> 5;
    const int lane = tid & 31;
    const int g    = lane >> 2;
    const int t    = lane & 3;

    const int blockRow = blockIdx.x * 128;
    const int blockCol = blockIdx.y * 128;
    const int warp_m = (wid & 3) * 32;
    const int warp_n = (wid >> 2) * 64;

    const int am0 = tid >> 2;
    const int akc = tid & 3;
    const int bk0 = tid >> 5;
    const int bnc = tid & 31;

    const int NIT = K >> 4;

    float acc[2][8][4];
#pragma unroll
    for (int mt = 0; mt < 2; mt++)
#pragma unroll
        for (int nt = 0; nt < 8; nt++)
#pragma unroll
            for (int i = 0; i < 4; i++) acc[mt][nt][i] = 0.0f;

    auto load_tiles = [&](int it, int stage) {
        const int k0 = it << 4;
        const uint32_t sa = smem_base + stage * STG;
        const uint32_t sb = sa + ASZ;
        {
            int r0 = blockRow + am0;
            int r1 = r0 + 64;
            const char* p0 = (const char*)(A + (size_t)r0 * lda + k0 + akc * 4);
            const char* p1 = (const char*)(A + (size_t)r1 * lda + k0 + akc * 4);
            cp_async16(sa + am0 * (ASTRIDE * 4) + akc * 16, p0, r0 < M ? 16 : 0);
            cp_async16(sa + (am0 + 64) * (ASTRIDE * 4) + akc * 16, p1, r1 < M ? 16 : 0);
        }
        {
            const char* p0 = (const char*)(W + (size_t)(k0 + bk0) * N + blockCol + bnc * 4);
            const char* p1 = (const char*)(W + (size_t)(k0 + bk0 + 8) * N + blockCol + bnc * 4);
            cp_async16(sb + bk0 * (BSTRIDE * 4) + bnc * 16, p0, 16);
            cp_async16(sb + (bk0 + 8) * (BSTRIDE * 4) + bnc * 16, p1, 16);
        }
        CP_ASYNC_COMMIT();
    };

    load_tiles(0, 0);
    int fetch = 1;

    for (int it = 0; it < NIT; it++) {
        CP_ASYNC_WAIT0();
        __syncthreads();
        if (fetch < NIT) { load_tiles(fetch, fetch & 1); fetch++; }

        const float* As = (const float*)(smem + (it & 1) * STG);
        const float* Bs = (const float*)(smem + (it & 1) * STG + ASZ);

#pragma unroll
        for (int ks = 0; ks < 2; ks++) {
            uint32_t a[2][4];
#pragma unroll
            for (int mt = 0; mt < 2; mt++) {
                const int m0 = warp_m + mt * 16 + g;
                const int kk = ks * 8 + t;
                a[mt][0] = tf32_round_bits(As[m0 * ASTRIDE + kk]);
                a[mt][1] = tf32_round_bits(As[(m0 + 8) * ASTRIDE + kk]);
                a[mt][2] = tf32_round_bits(As[m0 * ASTRIDE + kk + 4]);
                a[mt][3] = tf32_round_bits(As[(m0 + 8) * ASTRIDE + kk + 4]);
            }
            uint32_t b[8][2];
#pragma unroll
            for (int nt = 0; nt < 8; nt++) {
                const int n0 = warp_n + nt * 8 + g;
                const int kk = ks * 8 + t;
                b[nt][0] = __float_as_uint(Bs[kk * BSTRIDE + n0]);
                b[nt][1] = __float_as_uint(Bs[(kk + 4) * BSTRIDE + n0]);
            }
#pragma unroll
            for (int mt = 0; mt < 2; mt++)
#pragma unroll
                for (int nt = 0; nt < 8; nt++)
                    mma_tf32(acc[mt][nt][0], acc[mt][nt][1], acc[mt][nt][2], acc[mt][nt][3],
                             a[mt][0], a[mt][1], a[mt][2], a[mt][3],
                             b[nt][0], b[nt][1]);
        }
        __syncthreads();
    }

#pragma unroll
    for (int nt = 0; nt < 8; nt++) {
        const int col = blockCol + warp_n + nt * 8 + 2 * t;
        const float2 bv = *reinterpret_cast<const float2*>(&bias[col]);
#pragma unroll
        for (int mt = 0; mt < 2; mt++) {
#pragma unroll
            for (int half = 0; half < 2; half++) {
                const int row = blockRow + warp_m + mt * 16 + g + half * 8;
                if (row >= M) continue;
                float v0 = acc[mt][nt][half * 2 + 0] + bv.x;
                float v1 = acc[mt][nt][half * 2 + 1] + bv.y;
                if (relu) { v0 = fmaxf(v0, 0.f); v1 = fmaxf(v1, 0.f); }
                *reinterpret_cast<float2*>(C + (size_t)row * ldc + col) = make_float2(v0, v1);
            }
        }
    }
}

// ---------------------------------------------------------------------------
__global__ __launch_bounds__(256, 2)
void gemm_simt(const float* __restrict__ A, int lda,
               const float* __restrict__ W, int ldw,
               const float* __restrict__ bias,
               float* __restrict__ C, int ldc,
               int M, int N, int K, int relu)
{
    int gm = blockIdx.x * 64 + (threadIdx.x >> 2);
    int nq = (threadIdx.x & 3) * 8;
    if (gm >= M) return;
    float acc[8] = {0,0,0,0,0,0,0,0};
    const float* a = A + (size_t)gm * lda;
    for (int k = 0; k < K; k++) {
        float av = a[k];
        const float* wr = W + (size_t)k * ldw + nq;
#pragma unroll
        for (int j = 0; j < 8; j++) acc[j] = fmaf(av, wr[j], acc[j]);
    }
#pragma unroll
    for (int j = 0; j < 8; j++) {
        float v = acc[j] + bias[nq + j];
        if (relu) v = fmaxf(v, 0.0f);
        C[(size_t)gm * ldc + nq + j] = v;
    }
}

__global__ void final_kernel(const float* __restrict__ w,
                             const float* __restrict__ f3w,
                             const float* __restrict__ f3b,
                             float* __restrict__ out, int B)
{
    const int r = blockIdx.x * blockDim.x + threadIdx.x;
    if (r >= B) return;
    float s = 0.0f;
#pragma unroll
    for (int k = 0; k < 32; k++) s = fmaf(w[(size_t)r * 32 + k], f3w[k], s);
    out[r] = s + f3b[0];
}

// ---------------------------------------------------------------------------
extern "C" void kernel_launch(void* const* d_in, const int* in_sizes, int n_in,
                              void* d_out, int out_size)
{
    const float* pairs     = (const float*)d_in[0];
    const int*   idx_pairs = (const int*)  d_in[1];
    const float* aw  = (const float*)d_in[3];
    const float* ab  = (const float*)d_in[4];
    const float* bw  = (const float*)d_in[5];
    const float* bb  = (const float*)d_in[6];
    const float* p1w = (const float*)d_in[7];
    const float* p1b = (const float*)d_in[8];
    const float* p2w = (const float*)d_in[9];
    const float* p2b = (const float*)d_in[10];
    const float* p3w = (const float*)d_in[11];
    const float* p3b = (const float*)d_in[12];
    const float* f1w = (const float*)d_in[13];
    const float* f1b = (const float*)d_in[14];
    const float* f2w = (const float*)d_in[15];
    const float* f2b = (const float*)d_in[16];
    const float* f3w = (const float*)d_in[17];
    const float* f3b = (const float*)d_in[18];
    float* out = (float*)d_out;

    const int P = in_sizes[0] / 160;
    const int B = in_sizes[1];
    const int group = P / B;

    cudaFuncSetAttribute(fused_embed_p1,  cudaFuncAttributeMaxDynamicSharedMemorySize, SMEM_EP1);
    cudaFuncSetAttribute(fused_p2_segsum, cudaFuncAttributeMaxDynamicSharedMemorySize, SMEM_P2);

    __nv_bfloat16 *pairs_bf, *h512, *wbf;
    float *part, *hm, *y, *z, *w, *wtf;
    cudaGetSymbolAddress((void**)&pairs_bf, g_pairs_bf);
    cudaGetSymbolAddress((void**)&h512, g_h512);
    cudaGetSymbolAddress((void**)&part, g_part);
    cudaGetSymbolAddress((void**)&hm,   g_hm);
    cudaGetSymbolAddress((void**)&y,    g_y);
    cudaGetSymbolAddress((void**)&z,    g_z);
    cudaGetSymbolAddress((void**)&w,    g_w);
    cudaGetSymbolAddress((void**)&wbf,  g_wbf);
    cudaGetSymbolAddress((void**)&wtf,  g_wtf);

    __nv_bfloat16* awt = wbf;                    // [128][64]
    __nv_bfloat16* bwt = awt + 128 * 64;         // [128][32]
    __nv_bfloat16* p1t = bwt + 128 * 32;         // [512][384]
    __nv_bfloat16* p2t = p1t + 512 * 384;        // [256][512]
    float* p3r = wtf;                            // [256][1024]
    float* f1r = p3r + 256 * 1024;               // [1024][512]

    wt_bf16<<<(128 * 64  + 255) / 256, 256>>>(aw,  awt, 64, 128);
    wt_bf16<<<(128 * 32  + 255) / 256, 256>>>(bw,  bwt, 32, 128);
    wt_bf16<<<(512 * 384 + 255) / 256, 256>>>(p1w, p1t, 384, 512);
    wt_bf16<<<(256 * 512 + 255) / 256, 256>>>(p2w, p2t, 512, 256);
    round_copy<<<(256 * 1024 / 4 + 255) / 256, 256>>>(p3w, p3r, 256 * 1024 / 4);
    round_copy<<<(1024 * 512 / 4 + 255) / 256, 256>>>(f1w, f1r, 1024 * 512 / 4);
    zero_kernel<<<(2 * B * 256 + 255) / 256, 256>>>(part, 2 * B * 256);

    cvt_f32_bf16<<<((P * 160 / 2) + 255) / 256, 256>>>(pairs, pairs_bf, P * 160 / 2);

    const int NT = (P + 127) / 128;

    fused_embed_p1<<<NT, 256, SMEM_EP1>>>(pairs_bf, awt, bwt, ab, bb, p1t, p1b, h512, P);
    fused_p2_segsum<<<NT, 256, SMEM_P2>>>(h512, p2t, p2b, part, P, group, B);
    hm_combine<<<(B * 256 + 255) / 256, 256>>>(part, idx_pairs, hm, B);

    const int BT = (B + 127) / 128;
    tc_gemm_tf32<<<dim3(BT, 8), 256>>>(hm, 256, p3r, p3b, y, 1024, B, 1024, 256, 0);
    tc_gemm_tf32<<<dim3(BT, 4), 256>>>(y, 1024, f1r, f1b, z, 512,  B, 512, 1024, 1);
    gemm_simt<<<(B + 63) / 64, 256>>>(z, 512, f2w, 32, f2b, w, 32, B, 32, 512, 1);
    final_kernel<<<(B + 255) / 256, 256>>>(w, f3w, f3b, out, B);
}

// round 7
// speedup vs baseline: 1.0481x; 1.0481x over previous
#include <cuda_runtime.h>
#include <cuda_bf16.h>
#include <cstdint>

// ===========================================================================
// TGNN R7 — bf16 mma.sync pipeline, occupancy-preserving fusion only.
//   embed_all      : fp32 pairs -> (in-reg bf16) -> 3 embed GEMMs -> h384
//   tc_gemm_bf16   : h384 -> h512 (proven R4 kernel, 2 CTA/SM)
//   fused_p2_segsum: h512 -> p2 -> deterministic segment sums (2 CTA/SM)
//   batch: p3,f1 tf32 mma; f2/final SIMT fp32
// ===========================================================================

#define P_MAX  200000
#define B_MAX  2000

__device__ __nv_bfloat16 g_h384[(size_t)P_MAX * 384];
__device__ __nv_bfloat16 g_h512[(size_t)P_MAX * 512];
__device__ float g_part[2 * (size_t)B_MAX * 256];
__device__ float g_hm  [(size_t)B_MAX * 256];
__device__ float g_y   [(size_t)B_MAX * 1024];
__device__ float g_z   [(size_t)B_MAX * 512];
__device__ float g_w   [(size_t)B_MAX * 32];
__device__ __nv_bfloat16 g_wbf[1024 * 1024];
__device__ float g_wtf [1024 * 1024];

// ---------------------------------------------------------------------------
__device__ __forceinline__ float tf32_round(float x) {
    uint32_t r;
    asm("cvt.rna.tf32.f32 %0, %1;" : "=r"(r) : "f"(x));
    return __uint_as_float(r);
}
__device__ __forceinline__ uint32_t tf32_round_bits(float x) {
    uint32_t r;
    asm("cvt.rna.tf32.f32 %0, %1;" : "=r"(r) : "f"(x));
    return r;
}
__device__ __forceinline__ uint32_t bf2_bits(float lo, float hi) {
    __nv_bfloat162 p = __float22bfloat162_rn(make_float2(lo, hi));
    return *reinterpret_cast<uint32_t*>(&p);
}
__device__ __forceinline__ void cp_async16(uint32_t smem_addr, const void* gptr, int src_bytes) {
    asm volatile("cp.async.ca.shared.global [%0], [%1], 16, %2;\n"
                 :: "r"(smem_addr), "l"(gptr), "r"(src_bytes));
}
#define CP_ASYNC_COMMIT() asm volatile("cp.async.commit_group;\n" ::: "memory")
#define CP_ASYNC_WAIT0()  asm volatile("cp.async.wait_group 0;\n" ::: "memory")

__device__ __forceinline__ uint32_t smem_u32(const void* p) {
    uint32_t a;
    asm("{ .reg .u64 t; cvta.to.shared.u64 t, %1; cvt.u32.u64 %0, t; }" : "=r"(a) : "l"(p));
    return a;
}
__device__ __forceinline__ void mma_bf16(float& c0, float& c1, float& c2, float& c3,
                                         uint32_t a0, uint32_t a1, uint32_t a2, uint32_t a3,
                                         uint32_t b0, uint32_t b1) {
    asm volatile(
        "mma.sync.aligned.m16n8k16.row.col.f32.bf16.bf16.f32 "
        "{%0,%1,%2,%3}, {%4,%5,%6,%7}, {%8,%9}, {%0,%1,%2,%3};"
        : "+f"(c0), "+f"(c1), "+f"(c2), "+f"(c3)
        : "r"(a0), "r"(a1), "r"(a2), "r"(a3), "r"(b0), "r"(b1));
}
__device__ __forceinline__ void mma_tf32(float& c0, float& c1, float& c2, float& c3,
                                         uint32_t a0, uint32_t a1, uint32_t a2, uint32_t a3,
                                         uint32_t b0, uint32_t b1) {
    asm volatile(
        "mma.sync.aligned.m16n8k8.row.col.f32.tf32.tf32.f32 "
        "{%0,%1,%2,%3}, {%4,%5,%6,%7}, {%8,%9}, {%0,%1,%2,%3};"
        : "+f"(c0), "+f"(c1), "+f"(c2), "+f"(c3)
        : "r"(a0), "r"(a1), "r"(a2), "r"(a3), "r"(b0), "r"(b1));
}

// ---------------------------------------------------------------------------
// Shared bf16 GEMM building blocks.
//   Tile block = 128 rows x 32 k bf16; smem row = 64B data + 16B pad (80B).
// ---------------------------------------------------------------------------
#define TILE_B 10240

__device__ __forceinline__ void load_tile(uint32_t dst, const __nv_bfloat16* __restrict__ src,
                                          int ld, int rbase, int rmax, int k0, int tid)
{
#pragma unroll
    for (int h = 0; h < 2; h++) {
        const int chunk = tid + h * 256;
        const int row = chunk >> 2;
        const int ck  = chunk & 3;
        const int gr  = rbase + row;
        const char* p = (const char*)(src + (size_t)gr * ld + k0 + ck * 8);
        cp_async16(dst + row * 80 + ck * 16, p, gr < rmax ? 16 : 0);
    }
}

__device__ __forceinline__ void mma_block(const uint32_t* __restrict__ Aw,
                                          const uint32_t* __restrict__ Bw,
                                          float acc[2][8][4],
                                          int g, int t, int warp_m, int warp_n)
{
#pragma unroll
    for (int ks = 0; ks < 2; ks++) {
        const int kw = ks * 8 + t;
        uint32_t a[2][4];
#pragma unroll
        for (int mt = 0; mt < 2; mt++) {
            const int m0 = warp_m + mt * 16 + g;
            a[mt][0] = Aw[m0 * 20 + kw];
            a[mt][1] = Aw[(m0 + 8) * 20 + kw];
            a[mt][2] = Aw[m0 * 20 + kw + 4];
            a[mt][3] = Aw[(m0 + 8) * 20 + kw + 4];
        }
        uint32_t b[8][2];
#pragma unroll
        for (int nt = 0; nt < 8; nt++) {
            const int n0 = warp_n + nt * 8 + g;
            b[nt][0] = Bw[n0 * 20 + kw];
            b[nt][1] = Bw[n0 * 20 + kw + 4];
        }
#pragma unroll
        for (int mt = 0; mt < 2; mt++)
#pragma unroll
            for (int nt = 0; nt < 8; nt++)
                mma_bf16(acc[mt][nt][0], acc[mt][nt][1], acc[mt][nt][2], acc[mt][nt][3],
                         a[mt][0], a[mt][1], a[mt][2], a[mt][3],
                         b[nt][0], b[nt][1]);
    }
}

// ===========================================================================
// embed_all: one CTA = 128 rows, all three embed slabs.
//   smem: [0, 5*TILE_B)        A: 160 bf16 cols as 5 k-blocks
//         [51200, +2*TILE_B)   awt blocks (k0=0,32)
//         [71680, +TILE_B)     bwt block
//   Total 81920 B -> 2 CTA/SM.
// ===========================================================================
#define SMEM_EA (5 * TILE_B + 3 * TILE_B)   // 81920

__global__ __launch_bounds__(256)
void embed_all(const float* __restrict__ pairs,
               const __nv_bfloat16* __restrict__ awt,
               const __nv_bfloat16* __restrict__ bwt,
               const float* __restrict__ ab, const float* __restrict__ bb,
               __nv_bfloat16* __restrict__ h384, int P)
{
    extern __shared__ char smem[];
    const uint32_t smem_base = smem_u32(smem);

    const int tid = threadIdx.x;
    const int wid = tid >> 5, lane = tid & 31;
    const int g = lane >> 2, t = lane & 3;
    const int warp_m = (wid & 3) * 32;
    const int warp_n = (wid >> 2) * 64;
    const int blockRow = blockIdx.x * 128;

    // weights via cp.async
    load_tile(smem_base + 5 * TILE_B,           awt, 64, 0, 1 << 30, 0,  tid);
    load_tile(smem_base + 5 * TILE_B + TILE_B,  awt, 64, 0, 1 << 30, 32, tid);
    load_tile(smem_base + 7 * TILE_B,           bwt, 32, 0, 1 << 30, 0,  tid);
    CP_ASYNC_COMMIT();

    // A: fp32 LDG -> bf16 smem (row = tid>>1, half = tid&1)
    {
        const int r = tid >> 1;
        const int h = tid & 1;
        const int gr = blockRow + r;
        const bool ok = (gr < P);
        const float* rp = pairs + (size_t)gr * 160 + h * 80;
#pragma unroll
        for (int i = 0; i < 20; i++) {
            float4 v = ok ? *reinterpret_cast<const float4*>(rp + i * 4)
                          : make_float4(0.f, 0.f, 0.f, 0.f);
            const int col = h * 80 + i * 4;
            const int kb = col >> 5, kin = col & 31;
            uint2 pk;
            pk.x = bf2_bits(v.x, v.y);
            pk.y = bf2_bits(v.z, v.w);
            *reinterpret_cast<uint2*>(smem + kb * TILE_B + r * 80 + kin * 2) = pk;
        }
    }
    CP_ASYNC_WAIT0();
    __syncthreads();

    float acc[2][8][4];
    // slabs: c=0 (A blk 0,1 x awt), c=1 (A blk 2,3 x awt), c=2 (A blk 4 x bwt)
#pragma unroll
    for (int c = 0; c < 3; c++) {
        const int nkb = (c < 2) ? 2 : 1;
        const int ab0 = c * 2;
        const uint32_t woff = (c < 2) ? 5 * TILE_B : 7 * TILE_B;
        const float* biasc = (c < 2) ? ab : bb;

#pragma unroll
        for (int mt = 0; mt < 2; mt++)
#pragma unroll
            for (int nt = 0; nt < 8; nt++)
#pragma unroll
                for (int i = 0; i < 4; i++) acc[mt][nt][i] = 0.0f;

        for (int kb = 0; kb < nkb; kb++)
            mma_block((const uint32_t*)(smem + (ab0 + kb) * TILE_B),
                      (const uint32_t*)(smem + woff + kb * TILE_B),
                      acc, g, t, warp_m, warp_n);

#pragma unroll
        for (int nt = 0; nt < 8; nt++) {
            const int col = warp_n + nt * 8 + 2 * t;
            const float2 bv = *(const float2*)&biasc[col];
#pragma unroll
            for (int mt = 0; mt < 2; mt++)
#pragma unroll
                for (int half = 0; half < 2; half++) {
                    const int row = blockRow + warp_m + mt * 16 + half * 8 + g;
                    if (row >= P) continue;
                    float v0 = fmaxf(acc[mt][nt][half * 2 + 0] + bv.x, 0.f);
                    float v1 = fmaxf(acc[mt][nt][half * 2 + 1] + bv.y, 0.f);
                    *(__nv_bfloat162*)(h384 + (size_t)row * 384 + c * 128 + col) =
                        __float22bfloat162_rn(make_float2(v0, v1));
                }
        }
    }
}

// ===========================================================================
// tc_gemm_bf16 (proven R4): C = act(A @ WT^T + bias), 128x128x32 tiles.
// ===========================================================================
#define SMEM_BF (4 * TILE_B)

__global__ __launch_bounds__(256)
void tc_gemm_bf16(const __nv_bfloat16* __restrict__ A, int lda,
                  const __nv_bfloat16* __restrict__ WT,
                  const float* __restrict__ bias,
                  __nv_bfloat16* __restrict__ C, int ldc,
                  int M, int N, int K)
{
    __shared__ __align__(16) char smem[SMEM_BF];
    const uint32_t smem_base = smem_u32(smem);

    const int tid  = threadIdx.x;
    const int wid  = tid >> 5, lane = tid & 31;
    const int g    = lane >> 2, t = lane & 3;

    const int blockRow = blockIdx.x * 128;
    const int blockCol = blockIdx.y * 128;
    const int warp_m = (wid & 3) * 32;
    const int warp_n = (wid >> 2) * 64;

    const int NIT = K >> 5;

    float acc[2][8][4];
#pragma unroll
    for (int mt = 0; mt < 2; mt++)
#pragma unroll
        for (int nt = 0; nt < 8; nt++)
#pragma unroll
            for (int i = 0; i < 4; i++) acc[mt][nt][i] = 0.0f;

    load_tile(smem_base, A, lda, blockRow, M, 0, tid);
    load_tile(smem_base + 2 * TILE_B, WT, K, blockCol, 1 << 30, 0, tid);
    CP_ASYNC_COMMIT();

    for (int it = 0; it < NIT; it++) {
        CP_ASYNC_WAIT0();
        __syncthreads();
        if (it + 1 < NIT) {
            const int st = (it + 1) & 1;
            load_tile(smem_base + st * TILE_B, A, lda, blockRow, M, (it + 1) * 32, tid);
            load_tile(smem_base + 2 * TILE_B + st * TILE_B, WT, K, blockCol, 1 << 30,
                      (it + 1) * 32, tid);
            CP_ASYNC_COMMIT();
        }
        mma_block((const uint32_t*)(smem + (it & 1) * TILE_B),
                  (const uint32_t*)(smem + 2 * TILE_B + (it & 1) * TILE_B),
                  acc, g, t, warp_m, warp_n);
        __syncthreads();
    }

#pragma unroll
    for (int nt = 0; nt < 8; nt++) {
        const int col = blockCol + warp_n + nt * 8 + 2 * t;
        const float2 bv = *reinterpret_cast<const float2*>(&bias[col]);
#pragma unroll
        for (int mt = 0; mt < 2; mt++)
#pragma unroll
            for (int half = 0; half < 2; half++) {
                const int row = blockRow + warp_m + mt * 16 + half * 8 + g;
                if (row >= M) continue;
                float v0 = fmaxf(acc[mt][nt][half * 2 + 0] + bv.x, 0.f);
                float v1 = fmaxf(acc[mt][nt][half * 2 + 1] + bv.y, 0.f);
                *(__nv_bfloat162*)(C + (size_t)row * ldc + col) =
                    __float22bfloat162_rn(make_float2(v0, v1));
            }
    }
}

// ===========================================================================
// fused_p2_segsum (proven R5): p2 GEMM + deterministic segment sums.
// ===========================================================================
#define REDPAD 129
#define SMEM_P2 (4 * TILE_B + 128 * REDPAD * 4)   // 107008

__global__ __launch_bounds__(256)
void fused_p2_segsum(const __nv_bfloat16* __restrict__ h512,
                     const __nv_bfloat16* __restrict__ p2t,
                     const float* __restrict__ p2b,
                     float* __restrict__ part, int P, int group, int Bseg)
{
    extern __shared__ char smem[];
    const uint32_t smem_base = smem_u32(smem);
    const uint32_t stA = smem_base;
    const uint32_t stB = smem_base + 2 * TILE_B;
    float* red = (float*)(smem + 4 * TILE_B);

    const int tid = threadIdx.x;
    const int wid = tid >> 5, lane = tid & 31;
    const int g = lane >> 2, t = lane & 3;
    const int warp_m = (wid & 3) * 32;
    const int warp_n = (wid >> 2) * 64;
    const int blockRow = blockIdx.x * 128;

    float acc[2][8][4];

    for (int nc = 0; nc < 2; nc++) {
#pragma unroll
        for (int mt = 0; mt < 2; mt++)
#pragma unroll
            for (int nt = 0; nt < 8; nt++)
#pragma unroll
                for (int i = 0; i < 4; i++) acc[mt][nt][i] = 0.0f;

        load_tile(stA, h512, 512, blockRow, P, 0, tid);
        load_tile(stB, p2t, 512, nc * 128, 1 << 30, 0, tid);
        CP_ASYNC_COMMIT();

        for (int kb = 0; kb < 16; kb++) {
            CP_ASYNC_WAIT0();
            __syncthreads();
            if (kb + 1 < 16) {
                load_tile(stA + ((kb + 1) & 1) * TILE_B, h512, 512, blockRow, P,
                          (kb + 1) * 32, tid);
                load_tile(stB + ((kb + 1) & 1) * TILE_B, p2t, 512, nc * 128, 1 << 30,
                          (kb + 1) * 32, tid);
                CP_ASYNC_COMMIT();
            }
            mma_block((const uint32_t*)(smem + (kb & 1) * TILE_B),
                      (const uint32_t*)(smem + 2 * TILE_B + (kb & 1) * TILE_B),
                      acc, g, t, warp_m, warp_n);
            __syncthreads();
        }

#pragma unroll
        for (int nt = 0; nt < 8; nt++) {
            const int col = warp_n + nt * 8 + 2 * t;
            const float2 bv = *(const float2*)&p2b[nc * 128 + col];
#pragma unroll
            for (int mt = 0; mt < 2; mt++)
#pragma unroll
                for (int half = 0; half < 2; half++) {
                    const int row = warp_m + mt * 16 + half * 8 + g;
                    red[row * REDPAD + col]     = fmaxf(acc[mt][nt][half * 2 + 0] + bv.x, 0.f);
                    red[row * REDPAD + col + 1] = fmaxf(acc[mt][nt][half * 2 + 1] + bv.y, 0.f);
                }
        }
        __syncthreads();

        {
            const int col = tid & 127;
            const int rb  = (tid >> 7) * 64;
            float s = 0.f;
            bool any = false;
            int curseg = 0, nxt = 0;
            for (int r = rb; r < rb + 64; r++) {
                const int grow = blockRow + r;
                if (grow >= P) break;
                if (!any) {
                    curseg = grow / group;
                    nxt = (curseg + 1) * group;
                    any = true;
                } else if (grow >= nxt) {
                    const int slot = blockIdx.x - (curseg * group) / 128;
                    atomicAdd(&part[(size_t)slot * Bseg * 256 + curseg * 256 + nc * 128 + col], s);
                    s = 0.f;
                    curseg++;
                    nxt += group;
                }
                s += red[r * REDPAD + col];
            }
            if (any) {
                const int slot = blockIdx.x - (curseg * group) / 128;
                atomicAdd(&part[(size_t)slot * Bseg * 256 + curseg * 256 + nc * 128 + col], s);
            }
        }
        __syncthreads();
    }
}

// ---------------------------------------------------------------------------
__global__ void zero_kernel(float* __restrict__ p, int n)
{
    int i = blockIdx.x * blockDim.x + threadIdx.x;
    if (i < n) p[i] = 0.0f;
}

__global__ void hm_combine(const float* __restrict__ part, const int* __restrict__ idx,
                           float* __restrict__ hm, int Bseg)
{
    int i = blockIdx.x * blockDim.x + threadIdx.x;
    if (i >= Bseg * 256) return;
    int s = i >> 8;
    hm[i] = (part[i] + part[(size_t)Bseg * 256 + i]) / (float)idx[s];
}

// out[n*K + k] = bf16(in[k*N + n])
__global__ void wt_bf16(const float* __restrict__ in,
                        __nv_bfloat16* __restrict__ out, int K, int N)
{
    int i = blockIdx.x * blockDim.x + threadIdx.x;
    if (i >= K * N) return;
    int n = i / K, k = i % K;
    out[i] = __float2bfloat16(in[(size_t)k * N + n]);
}

__global__ void round_copy(const float* __restrict__ src, float* __restrict__ dst, int n4)
{
    int i = blockIdx.x * blockDim.x + threadIdx.x;
    if (i >= n4) return;
    float4 v = reinterpret_cast<const float4*>(src)[i];
    v.x = tf32_round(v.x); v.y = tf32_round(v.y);
    v.z = tf32_round(v.z); v.w = tf32_round(v.w);
    reinterpret_cast<float4*>(dst)[i] = v;
}

// ===========================================================================
// tf32 tensor GEMM (proven) — batch layers p3, f1
// ===========================================================================
#define ASTRIDE 20
#define BSTRIDE 136
#define ASZ (128 * ASTRIDE * 4)
#define BSZ (16 * BSTRIDE * 4)
#define STG (ASZ + BSZ)
#define SMEM_TF (2 * STG)

__global__ __launch_bounds__(256)
void tc_gemm_tf32(const float* __restrict__ A, int lda,
                  const float* __restrict__ W,
                  const float* __restrict__ bias,
                  float* __restrict__ C, int ldc,
                  int M, int N, int K, int relu)
{
    __shared__ __align__(16) char smem[SMEM_TF];
    const uint32_t smem_base = smem_u32(smem);

    const int tid  = threadIdx.x;
    const int wid  = tid >> 5, lane = tid & 31;
    const int g    = lane >> 2, t = lane & 3;

    const int blockRow = blockIdx.x * 128;
    const int blockCol = blockIdx.y * 128;
    const int warp_m = (wid & 3) * 32;
    const int warp_n = (wid >> 2) * 64;

    const int am0 = tid >> 2;
    const int akc = tid & 3;
    const int bk0 = tid >> 5;
    const int bnc = tid & 31;

    const int NIT = K >> 4;

    float acc[2][8][4];
#pragma unroll
    for (int mt = 0; mt < 2; mt++)
#pragma unroll
        for (int nt = 0; nt < 8; nt++)
#pragma unroll
            for (int i = 0; i < 4; i++) acc[mt][nt][i] = 0.0f;

    auto load_tiles = [&](int it, int stage) {
        const int k0 = it << 4;
        const uint32_t sa = smem_base + stage * STG;
        const uint32_t sb = sa + ASZ;
        {
            int r0 = blockRow + am0;
            int r1 = r0 + 64;
            const char* p0 = (const char*)(A + (size_t)r0 * lda + k0 + akc * 4);
            const char* p1 = (const char*)(A + (size_t)r1 * lda + k0 + akc * 4);
            cp_async16(sa + am0 * (ASTRIDE * 4) + akc * 16, p0, r0 < M ? 16 : 0);
            cp_async16(sa + (am0 + 64) * (ASTRIDE * 4) + akc * 16, p1, r1 < M ? 16 : 0);
        }
        {
            const char* p0 = (const char*)(W + (size_t)(k0 + bk0) * N + blockCol + bnc * 4);
            const char* p1 = (const char*)(W + (size_t)(k0 + bk0 + 8) * N + blockCol + bnc * 4);
            cp_async16(sb + bk0 * (BSTRIDE * 4) + bnc * 16, p0, 16);
            cp_async16(sb + (bk0 + 8) * (BSTRIDE * 4) + bnc * 16, p1, 16);
        }
        CP_ASYNC_COMMIT();
    };

    load_tiles(0, 0);
    int fetch = 1;

    for (int it = 0; it < NIT; it++) {
        CP_ASYNC_WAIT0();
        __syncthreads();
        if (fetch < NIT) { load_tiles(fetch, fetch & 1); fetch++; }

        const float* As = (const float*)(smem + (it & 1) * STG);
        const float* Bs = (const float*)(smem + (it & 1) * STG + ASZ);

#pragma unroll
        for (int ks = 0; ks < 2; ks++) {
            uint32_t a[2][4];
#pragma unroll
            for (int mt = 0; mt < 2; mt++) {
                const int m0 = warp_m + mt * 16 + g;
                const int kk = ks * 8 + t;
                a[mt][0] = tf32_round_bits(As[m0 * ASTRIDE + kk]);
                a[mt][1] = tf32_round_bits(As[(m0 + 8) * ASTRIDE + kk]);
                a[mt][2] = tf32_round_bits(As[m0 * ASTRIDE + kk + 4]);
                a[mt][3] = tf32_round_bits(As[(m0 + 8) * ASTRIDE + kk + 4]);
            }
            uint32_t b[8][2];
#pragma unroll
            for (int nt = 0; nt < 8; nt++) {
                const int n0 = warp_n + nt * 8 + g;
                const int kk = ks * 8 + t;
                b[nt][0] = __float_as_uint(Bs[kk * BSTRIDE + n0]);
                b[nt][1] = __float_as_uint(Bs[(kk + 4) * BSTRIDE + n0]);
            }
#pragma unroll
            for (int mt = 0; mt < 2; mt++)
#pragma unroll
                for (int nt = 0; nt < 8; nt++)
                    mma_tf32(acc[mt][nt][0], acc[mt][nt][1], acc[mt][nt][2], acc[mt][nt][3],
                             a[mt][0], a[mt][1], a[mt][2], a[mt][3],
                             b[nt][0], b[nt][1]);
        }
        __syncthreads();
    }

#pragma unroll
    for (int nt = 0; nt < 8; nt++) {
        const int col = blockCol + warp_n + nt * 8 + 2 * t;
        const float2 bv = *reinterpret_cast<const float2*>(&bias[col]);
#pragma unroll
        for (int mt = 0; mt < 2; mt++) {
#pragma unroll
            for (int half = 0; half < 2; half++) {
                const int row = blockRow + warp_m + mt * 16 + g + half * 8;
                if (row >= M) continue;
                float v0 = acc[mt][nt][half * 2 + 0] + bv.x;
                float v1 = acc[mt][nt][half * 2 + 1] + bv.y;
                if (relu) { v0 = fmaxf(v0, 0.f); v1 = fmaxf(v1, 0.f); }
                *reinterpret_cast<float2*>(C + (size_t)row * ldc + col) = make_float2(v0, v1);
            }
        }
    }
}

// ---------------------------------------------------------------------------
__global__ __launch_bounds__(256, 2)
void gemm_simt(const float* __restrict__ A, int lda,
               const float* __restrict__ W, int ldw,
               const float* __restrict__ bias,
               float* __restrict__ C, int ldc,
               int M, int N, int K, int relu)
{
    int gm = blockIdx.x * 64 + (threadIdx.x >> 2);
    int nq = (threadIdx.x & 3) * 8;
    if (gm >= M) return;
    float acc[8] = {0,0,0,0,0,0,0,0};
    const float* a = A + (size_t)gm * lda;
    for (int k = 0; k < K; k++) {
        float av = a[k];
        const float* wr = W + (size_t)k * ldw + nq;
#pragma unroll
        for (int j = 0; j < 8; j++) acc[j] = fmaf(av, wr[j], acc[j]);
    }
#pragma unroll
    for (int j = 0; j < 8; j++) {
        float v = acc[j] + bias[nq + j];
        if (relu) v = fmaxf(v, 0.0f);
        C[(size_t)gm * ldc + nq + j] = v;
    }
}

__global__ void final_kernel(const float* __restrict__ w,
                             const float* __restrict__ f3w,
                             const float* __restrict__ f3b,
                             float* __restrict__ out, int B)
{
    const int r = blockIdx.x * blockDim.x + threadIdx.x;
    if (r >= B) return;
    float s = 0.0f;
#pragma unroll
    for (int k = 0; k < 32; k++) s = fmaf(w[(size_t)r * 32 + k], f3w[k], s);
    out[r] = s + f3b[0];
}

// ---------------------------------------------------------------------------
extern "C" void kernel_launch(void* const* d_in, const int* in_sizes, int n_in,
                              void* d_out, int out_size)
{
    const float* pairs     = (const float*)d_in[0];
    const int*   idx_pairs = (const int*)  d_in[1];
    const float* aw  = (const float*)d_in[3];
    const float* ab  = (const float*)d_in[4];
    const float* bw  = (const float*)d_in[5];
    const float* bb  = (const float*)d_in[6];
    const float* p1w = (const float*)d_in[7];
    const float* p1b = (const float*)d_in[8];
    const float* p2w = (const float*)d_in[9];
    const float* p2b = (const float*)d_in[10];
    const float* p3w = (const float*)d_in[11];
    const float* p3b = (const float*)d_in[12];
    const float* f1w = (const float*)d_in[13];
    const float* f1b = (const float*)d_in[14];
    const float* f2w = (const float*)d_in[15];
    const float* f2b = (const float*)d_in[16];
    const float* f3w = (const float*)d_in[17];
    const float* f3b = (const float*)d_in[18];
    float* out = (float*)d_out;

    const int P = in_sizes[0] / 160;
    const int B = in_sizes[1];
    const int group = P / B;

    cudaFuncSetAttribute(embed_all,       cudaFuncAttributeMaxDynamicSharedMemorySize, SMEM_EA);
    cudaFuncSetAttribute(fused_p2_segsum, cudaFuncAttributeMaxDynamicSharedMemorySize, SMEM_P2);

    __nv_bfloat16 *h384, *h512, *wbf;
    float *part, *hm, *y, *z, *w, *wtf;
    cudaGetSymbolAddress((void**)&h384, g_h384);
    cudaGetSymbolAddress((void**)&h512, g_h512);
    cudaGetSymbolAddress((void**)&part, g_part);
    cudaGetSymbolAddress((void**)&hm,   g_hm);
    cudaGetSymbolAddress((void**)&y,    g_y);
    cudaGetSymbolAddress((void**)&z,    g_z);
    cudaGetSymbolAddress((void**)&w,    g_w);
    cudaGetSymbolAddress((void**)&wbf,  g_wbf);
    cudaGetSymbolAddress((void**)&wtf,  g_wtf);

    __nv_bfloat16* awt = wbf;                    // [128][64]
    __nv_bfloat16* bwt = awt + 128 * 64;         // [128][32]
    __nv_bfloat16* p1t = bwt + 128 * 32;         // [512][384]
    __nv_bfloat16* p2t = p1t + 512 * 384;        // [256][512]
    float* p3r = wtf;                            // [256][1024]
    float* f1r = p3r + 256 * 1024;               // [1024][512]

    wt_bf16<<<(128 * 64  + 255) / 256, 256>>>(aw,  awt, 64, 128);
    wt_bf16<<<(128 * 32  + 255) / 256, 256>>>(bw,  bwt, 32, 128);
    wt_bf16<<<(512 * 384 + 255) / 256, 256>>>(p1w, p1t, 384, 512);
    wt_bf16<<<(256 * 512 + 255) / 256, 256>>>(p2w, p2t, 512, 256);
    round_copy<<<(256 * 1024 / 4 + 255) / 256, 256>>>(p3w, p3r, 256 * 1024 / 4);
    round_copy<<<(1024 * 512 / 4 + 255) / 256, 256>>>(f1w, f1r, 1024 * 512 / 4);
    zero_kernel<<<(2 * B * 256 + 255) / 256, 256>>>(part, 2 * B * 256);

    const int NT = (P + 127) / 128;

    embed_all<<<NT, 256, SMEM_EA>>>(pairs, awt, bwt, ab, bb, h384, P);
    tc_gemm_bf16<<<dim3(NT, 4), 256>>>(h384, 384, p1t, p1b, h512, 512, P, 512, 384);
    fused_p2_segsum<<<NT, 256, SMEM_P2>>>(h512, p2t, p2b, part, P, group, B);
    hm_combine<<<(B * 256 + 255) / 256, 256>>>(part, idx_pairs, hm, B);

    const int BT = (B + 127) / 128;
    tc_gemm_tf32<<<dim3(BT, 8), 256>>>(hm, 256, p3r, p3b, y, 1024, B, 1024, 256, 0);
    tc_gemm_tf32<<<dim3(BT, 4), 256>>>(y, 1024, f1r, f1b, z, 512,  B, 512, 1024, 1);
    gemm_simt<<<(B + 63) / 64, 256>>>(z, 512, f2w, 32, f2b, w, 32, B, 32, 512, 1);
    final_kernel<<<(B + 255) / 256, 256>>>(w, f3w, f3b, out, B);
}

// round 8
// speedup vs baseline: 1.3043x; 1.2444x over previous
#include <cuda_runtime.h>
#include <cuda_bf16.h>
#include <cstdint>

// ===========================================================================
// TGNN R8 — bf16 mma.sync pipeline with ldmatrix + 3-stage cp.async.
//   embed_all      : fp32 pairs -> (in-reg bf16) -> 3 embed GEMMs -> h384
//   tc_gemm_bf16   : h384 -> h512 (3-stage pipeline, 1 barrier/k-block)
//   fused_p2_segsum: h512 -> p2 -> deterministic segment sums (3-stage,
//                    reduction tile aliases pipeline stages)
//   batch: p3,f1 tf32 mma; f2/final SIMT fp32
// ===========================================================================

#define P_MAX  200000
#define B_MAX  2000

__device__ __nv_bfloat16 g_h384[(size_t)P_MAX * 384];
__device__ __nv_bfloat16 g_h512[(size_t)P_MAX * 512];
__device__ float g_part[2 * (size_t)B_MAX * 256];
__device__ float g_hm  [(size_t)B_MAX * 256];
__device__ float g_y   [(size_t)B_MAX * 1024];
__device__ float g_z   [(size_t)B_MAX * 512];
__device__ float g_w   [(size_t)B_MAX * 32];
__device__ __nv_bfloat16 g_wbf[1024 * 1024];
__device__ float g_wtf [1024 * 1024];

// ---------------------------------------------------------------------------
__device__ __forceinline__ float tf32_round(float x) {
    uint32_t r;
    asm("cvt.rna.tf32.f32 %0, %1;" : "=r"(r) : "f"(x));
    return __uint_as_float(r);
}
__device__ __forceinline__ uint32_t tf32_round_bits(float x) {
    uint32_t r;
    asm("cvt.rna.tf32.f32 %0, %1;" : "=r"(r) : "f"(x));
    return r;
}
__device__ __forceinline__ uint32_t bf2_bits(float lo, float hi) {
    __nv_bfloat162 p = __float22bfloat162_rn(make_float2(lo, hi));
    return *reinterpret_cast<uint32_t*>(&p);
}
__device__ __forceinline__ void cp_async16(uint32_t smem_addr, const void* gptr, int src_bytes) {
    asm volatile("cp.async.ca.shared.global [%0], [%1], 16, %2;\n"
                 :: "r"(smem_addr), "l"(gptr), "r"(src_bytes));
}
#define CP_ASYNC_COMMIT() asm volatile("cp.async.commit_group;\n" ::: "memory")
#define CP_ASYNC_WAIT0()  asm volatile("cp.async.wait_group 0;\n" ::: "memory")
#define CP_ASYNC_WAIT1()  asm volatile("cp.async.wait_group 1;\n" ::: "memory")

__device__ __forceinline__ uint32_t smem_u32(const void* p) {
    uint32_t a;
    asm("{ .reg .u64 t; cvta.to.shared.u64 t, %1; cvt.u32.u64 %0, t; }" : "=r"(a) : "l"(p));
    return a;
}
__device__ __forceinline__ void mma_bf16(float& c0, float& c1, float& c2, float& c3,
                                         uint32_t a0, uint32_t a1, uint32_t a2, uint32_t a3,
                                         uint32_t b0, uint32_t b1) {
    asm volatile(
        "mma.sync.aligned.m16n8k16.row.col.f32.bf16.bf16.f32 "
        "{%0,%1,%2,%3}, {%4,%5,%6,%7}, {%8,%9}, {%0,%1,%2,%3};"
        : "+f"(c0), "+f"(c1), "+f"(c2), "+f"(c3)
        : "r"(a0), "r"(a1), "r"(a2), "r"(a3), "r"(b0), "r"(b1));
}
__device__ __forceinline__ void mma_tf32(float& c0, float& c1, float& c2, float& c3,
                                         uint32_t a0, uint32_t a1, uint32_t a2, uint32_t a3,
                                         uint32_t b0, uint32_t b1) {
    asm volatile(
        "mma.sync.aligned.m16n8k8.row.col.f32.tf32.tf32.f32 "
        "{%0,%1,%2,%3}, {%4,%5,%6,%7}, {%8,%9}, {%0,%1,%2,%3};"
        : "+f"(c0), "+f"(c1), "+f"(c2), "+f"(c3)
        : "r"(a0), "r"(a1), "r"(a2), "r"(a3), "r"(b0), "r"(b1));
}
__device__ __forceinline__ void ldsm_x4(uint32_t* r, uint32_t addr) {
    asm volatile("ldmatrix.sync.aligned.m8n8.x4.shared.b16 {%0,%1,%2,%3}, [%4];"
                 : "=r"(r[0]), "=r"(r[1]), "=r"(r[2]), "=r"(r[3]) : "r"(addr));
}

// ---------------------------------------------------------------------------
// Shared bf16 GEMM building blocks.
//   Tile block = 128 rows x 32 k bf16; smem row = 64B data + 16B pad (80B).
// ---------------------------------------------------------------------------
#define TILE_B 10240

__device__ __forceinline__ void load_tile(uint32_t dst, const __nv_bfloat16* __restrict__ src,
                                          int ld, int rbase, int rmax, int k0, int tid)
{
#pragma unroll
    for (int h = 0; h < 2; h++) {
        const int chunk = tid + h * 256;
        const int row = chunk >> 2;
        const int ck  = chunk & 3;
        const int gr  = rbase + row;
        const char* p = (const char*)(src + (size_t)gr * ld + k0 + ck * 8);
        cp_async16(dst + row * 80 + ck * 16, p, gr < rmax ? 16 : 0);
    }
}

// ldmatrix-based k32 block: A[128][32] @ B[128][32]^T fragments.
// A frag x4: matrices (m0-7,k0-7),(m8-15,k0-7),(m0-7,k8-15),(m8-15,k8-15)
// B frag x4 covers 2 n-tiles: (n0-7,kh0),(n0-7,kh1),(n8-15,kh0),(n8-15,kh1)
__device__ __forceinline__ void mma_block_ldsm(uint32_t Abase, uint32_t Bbase,
                                               float acc[2][8][4],
                                               int lane, int warp_m, int warp_n)
{
    const int l7  = lane & 7;
    const int lb3 = (lane >> 3) & 1;
    const int lb4 = lane >> 4;
#pragma unroll
    for (int ks = 0; ks < 2; ks++) {
        uint32_t a[2][4];
#pragma unroll
        for (int mt = 0; mt < 2; mt++) {
            uint32_t addr = Abase + (uint32_t)(warp_m + mt * 16 + lb3 * 8 + l7) * 80
                          + ks * 32 + lb4 * 16;
            ldsm_x4(a[mt], addr);
        }
        uint32_t b[8][2];
#pragma unroll
        for (int np = 0; np < 4; np++) {
            uint32_t r[4];
            uint32_t addr = Bbase + (uint32_t)(warp_n + np * 16 + lb4 * 8 + l7) * 80
                          + ks * 32 + lb3 * 16;
            ldsm_x4(r, addr);
            b[2 * np][0]     = r[0];
            b[2 * np][1]     = r[1];
            b[2 * np + 1][0] = r[2];
            b[2 * np + 1][1] = r[3];
        }
#pragma unroll
        for (int mt = 0; mt < 2; mt++)
#pragma unroll
            for (int nt = 0; nt < 8; nt++)
                mma_bf16(acc[mt][nt][0], acc[mt][nt][1], acc[mt][nt][2], acc[mt][nt][3],
                         a[mt][0], a[mt][1], a[mt][2], a[mt][3],
                         b[nt][0], b[nt][1]);
    }
}

// ===========================================================================
// embed_all: one CTA = 128 rows, all three embed slabs (81920 B smem).
// ===========================================================================
#define SMEM_EA (5 * TILE_B + 3 * TILE_B)   // 81920

__global__ __launch_bounds__(256)
void embed_all(const float* __restrict__ pairs,
               const __nv_bfloat16* __restrict__ awt,
               const __nv_bfloat16* __restrict__ bwt,
               const float* __restrict__ ab, const float* __restrict__ bb,
               __nv_bfloat16* __restrict__ h384, int P)
{
    extern __shared__ char smem[];
    const uint32_t smem_base = smem_u32(smem);

    const int tid = threadIdx.x;
    const int wid = tid >> 5, lane = tid & 31;
    const int g = lane >> 2, t = lane & 3;
    const int warp_m = (wid & 3) * 32;
    const int warp_n = (wid >> 2) * 64;
    const int blockRow = blockIdx.x * 128;

    load_tile(smem_base + 5 * TILE_B,           awt, 64, 0, 1 << 30, 0,  tid);
    load_tile(smem_base + 5 * TILE_B + TILE_B,  awt, 64, 0, 1 << 30, 32, tid);
    load_tile(smem_base + 7 * TILE_B,           bwt, 32, 0, 1 << 30, 0,  tid);
    CP_ASYNC_COMMIT();

    {
        const int r = tid >> 1;
        const int h = tid & 1;
        const int gr = blockRow + r;
        const bool ok = (gr < P);
        const float* rp = pairs + (size_t)gr * 160 + h * 80;
#pragma unroll
        for (int i = 0; i < 20; i++) {
            float4 v = ok ? *reinterpret_cast<const float4*>(rp + i * 4)
                          : make_float4(0.f, 0.f, 0.f, 0.f);
            const int col = h * 80 + i * 4;
            const int kb = col >> 5, kin = col & 31;
            uint2 pk;
            pk.x = bf2_bits(v.x, v.y);
            pk.y = bf2_bits(v.z, v.w);
            *reinterpret_cast<uint2*>(smem + kb * TILE_B + r * 80 + kin * 2) = pk;
        }
    }
    CP_ASYNC_WAIT0();
    __syncthreads();

    float acc[2][8][4];
#pragma unroll
    for (int c = 0; c < 3; c++) {
        const int nkb = (c < 2) ? 2 : 1;
        const int ab0 = c * 2;
        const uint32_t woff = (c < 2) ? 5 * TILE_B : 7 * TILE_B;
        const float* biasc = (c < 2) ? ab : bb;

#pragma unroll
        for (int mt = 0; mt < 2; mt++)
#pragma unroll
            for (int nt = 0; nt < 8; nt++)
#pragma unroll
                for (int i = 0; i < 4; i++) acc[mt][nt][i] = 0.0f;

        for (int kb = 0; kb < nkb; kb++)
            mma_block_ldsm(smem_base + (ab0 + kb) * TILE_B,
                           smem_base + woff + kb * TILE_B,
                           acc, lane, warp_m, warp_n);

#pragma unroll
        for (int nt = 0; nt < 8; nt++) {
            const int col = warp_n + nt * 8 + 2 * t;
            const float2 bv = *(const float2*)&biasc[col];
#pragma unroll
            for (int mt = 0; mt < 2; mt++)
#pragma unroll
                for (int half = 0; half < 2; half++) {
                    const int row = blockRow + warp_m + mt * 16 + half * 8 + g;
                    if (row >= P) continue;
                    float v0 = fmaxf(acc[mt][nt][half * 2 + 0] + bv.x, 0.f);
                    float v1 = fmaxf(acc[mt][nt][half * 2 + 1] + bv.y, 0.f);
                    *(__nv_bfloat162*)(h384 + (size_t)row * 384 + c * 128 + col) =
                        __float22bfloat162_rn(make_float2(v0, v1));
                }
        }
    }
}

// ===========================================================================
// tc_gemm_bf16 (p1): 3-stage cp.async pipeline, 1 barrier per k-block.
//   dynamic smem = 6 * TILE_B = 61440; stage s: A at s*2*TILE_B, B at +TILE_B
// ===========================================================================
#define SMEM_BF3 (6 * TILE_B)

__global__ __launch_bounds__(256)
void tc_gemm_bf16(const __nv_bfloat16* __restrict__ A, int lda,
                  const __nv_bfloat16* __restrict__ WT,
                  const float* __restrict__ bias,
                  __nv_bfloat16* __restrict__ C, int ldc,
                  int M, int N, int K)
{
    extern __shared__ char smem[];
    const uint32_t smem_base = smem_u32(smem);

    const int tid  = threadIdx.x;
    const int wid  = tid >> 5, lane = tid & 31;
    const int g    = lane >> 2, t = lane & 3;

    const int blockRow = blockIdx.x * 128;
    const int blockCol = blockIdx.y * 128;
    const int warp_m = (wid & 3) * 32;
    const int warp_n = (wid >> 2) * 64;

    const int NIT = K >> 5;   // assumed >= 2

    float acc[2][8][4];
#pragma unroll
    for (int mt = 0; mt < 2; mt++)
#pragma unroll
        for (int nt = 0; nt < 8; nt++)
#pragma unroll
            for (int i = 0; i < 4; i++) acc[mt][nt][i] = 0.0f;

    auto load_stage = [&](int it) {
        const uint32_t base = smem_base + (it % 3) * (2 * TILE_B);
        load_tile(base, A, lda, blockRow, M, it * 32, tid);
        load_tile(base + TILE_B, WT, K, blockCol, 1 << 30, it * 32, tid);
        CP_ASYNC_COMMIT();
    };

    load_stage(0);
    load_stage(1);

    for (int it = 0; it < NIT; it++) {
        if (it + 1 < NIT) { CP_ASYNC_WAIT1(); } else { CP_ASYNC_WAIT0(); }
        __syncthreads();
        const uint32_t base = smem_base + (it % 3) * (2 * TILE_B);
        mma_block_ldsm(base, base + TILE_B, acc, lane, warp_m, warp_n);
        if (it + 2 < NIT) load_stage(it + 2);
    }

#pragma unroll
    for (int nt = 0; nt < 8; nt++) {
        const int col = blockCol + warp_n + nt * 8 + 2 * t;
        const float2 bv = *reinterpret_cast<const float2*>(&bias[col]);
#pragma unroll
        for (int mt = 0; mt < 2; mt++)
#pragma unroll
            for (int half = 0; half < 2; half++) {
                const int row = blockRow + warp_m + mt * 16 + half * 8 + g;
                if (row >= M) continue;
                float v0 = fmaxf(acc[mt][nt][half * 2 + 0] + bv.x, 0.f);
                float v1 = fmaxf(acc[mt][nt][half * 2 + 1] + bv.y, 0.f);
                *(__nv_bfloat162*)(C + (size_t)row * ldc + col) =
                    __float22bfloat162_rn(make_float2(v0, v1));
            }
    }
}

// ===========================================================================
// fused_p2_segsum: 3-stage pipeline; fp32 reduction tile ALIASES the stages
// (only used after the k-loop fully drains). smem = 128*129*4 = 66048.
// ===========================================================================
#define REDPAD 129
#define SMEM_P2 (128 * REDPAD * 4)   // 66048 >= 6*TILE_B (61440)

__global__ __launch_bounds__(256)
void fused_p2_segsum(const __nv_bfloat16* __restrict__ h512,
                     const __nv_bfloat16* __restrict__ p2t,
                     const float* __restrict__ p2b,
                     float* __restrict__ part, int P, int group, int Bseg)
{
    extern __shared__ char smem[];
    const uint32_t smem_base = smem_u32(smem);
    float* red = (float*)smem;

    const int tid = threadIdx.x;
    const int wid = tid >> 5, lane = tid & 31;
    const int g = lane >> 2, t = lane & 3;
    const int warp_m = (wid & 3) * 32;
    const int warp_n = (wid >> 2) * 64;
    const int blockRow = blockIdx.x * 128;

    float acc[2][8][4];

    for (int nc = 0; nc < 2; nc++) {
#pragma unroll
        for (int mt = 0; mt < 2; mt++)
#pragma unroll
            for (int nt = 0; nt < 8; nt++)
#pragma unroll
                for (int i = 0; i < 4; i++) acc[mt][nt][i] = 0.0f;

        auto load_stage = [&](int kb) {
            const uint32_t base = smem_base + (kb % 3) * (2 * TILE_B);
            load_tile(base, h512, 512, blockRow, P, kb * 32, tid);
            load_tile(base + TILE_B, p2t, 512, nc * 128, 1 << 30, kb * 32, tid);
            CP_ASYNC_COMMIT();
        };

        load_stage(0);
        load_stage(1);

        for (int kb = 0; kb < 16; kb++) {
            if (kb + 1 < 16) { CP_ASYNC_WAIT1(); } else { CP_ASYNC_WAIT0(); }
            __syncthreads();
            const uint32_t base = smem_base + (kb % 3) * (2 * TILE_B);
            mma_block_ldsm(base, base + TILE_B, acc, lane, warp_m, warp_n);
            if (kb + 2 < 16) load_stage(kb + 2);
        }
        __syncthreads();   // all mma reads done before red overwrites stages

#pragma unroll
        for (int nt = 0; nt < 8; nt++) {
            const int col = warp_n + nt * 8 + 2 * t;
            const float2 bv = *(const float2*)&p2b[nc * 128 + col];
#pragma unroll
            for (int mt = 0; mt < 2; mt++)
#pragma unroll
                for (int half = 0; half < 2; half++) {
                    const int row = warp_m + mt * 16 + half * 8 + g;
                    red[row * REDPAD + col]     = fmaxf(acc[mt][nt][half * 2 + 0] + bv.x, 0.f);
                    red[row * REDPAD + col + 1] = fmaxf(acc[mt][nt][half * 2 + 1] + bv.y, 0.f);
                }
        }
        __syncthreads();

        {
            const int col = tid & 127;
            const int rb  = (tid >> 7) * 64;
            float s = 0.f;
            bool any = false;
            int curseg = 0, nxt = 0;
            for (int r = rb; r < rb + 64; r++) {
                const int grow = blockRow + r;
                if (grow >= P) break;
                if (!any) {
                    curseg = grow / group;
                    nxt = (curseg + 1) * group;
                    any = true;
                } else if (grow >= nxt) {
                    const int slot = blockIdx.x - (curseg * group) / 128;
                    atomicAdd(&part[(size_t)slot * Bseg * 256 + curseg * 256 + nc * 128 + col], s);
                    s = 0.f;
                    curseg++;
                    nxt += group;
                }
                s += red[r * REDPAD + col];
            }
            if (any) {
                const int slot = blockIdx.x - (curseg * group) / 128;
                atomicAdd(&part[(size_t)slot * Bseg * 256 + curseg * 256 + nc * 128 + col], s);
            }
        }
        __syncthreads();
    }
}

// ---------------------------------------------------------------------------
__global__ void zero_kernel(float* __restrict__ p, int n)
{
    int i = blockIdx.x * blockDim.x + threadIdx.x;
    if (i < n) p[i] = 0.0f;
}

__global__ void hm_combine(const float* __restrict__ part, const int* __restrict__ idx,
                           float* __restrict__ hm, int Bseg)
{
    int i = blockIdx.x * blockDim.x + threadIdx.x;
    if (i >= Bseg * 256) return;
    int s = i >> 8;
    hm[i] = (part[i] + part[(size_t)Bseg * 256 + i]) / (float)idx[s];
}

// out[n*K + k] = bf16(in[k*N + n])
__global__ void wt_bf16(const float* __restrict__ in,
                        __nv_bfloat16* __restrict__ out, int K, int N)
{
    int i = blockIdx.x * blockDim.x + threadIdx.x;
    if (i >= K * N) return;
    int n = i / K, k = i % K;
    out[i] = __float2bfloat16(in[(size_t)k * N + n]);
}

__global__ void round_copy(const float* __restrict__ src, float* __restrict__ dst, int n4)
{
    int i = blockIdx.x * blockDim.x + threadIdx.x;
    if (i >= n4) return;
    float4 v = reinterpret_cast<const float4*>(src)[i];
    v.x = tf32_round(v.x); v.y = tf32_round(v.y);
    v.z = tf32_round(v.z); v.w = tf32_round(v.w);
    reinterpret_cast<float4*>(dst)[i] = v;
}

// ===========================================================================
// tf32 tensor GEMM (proven) — batch layers p3, f1
// ===========================================================================
#define ASTRIDE 20
#define BSTRIDE 136
#define ASZ (128 * ASTRIDE * 4)
#define BSZ (16 * BSTRIDE * 4)
#define STG (ASZ + BSZ)
#define SMEM_TF (2 * STG)

__global__ __launch_bounds__(256)
void tc_gemm_tf32(const float* __restrict__ A, int lda,
                  const float* __restrict__ W,
                  const float* __restrict__ bias,
                  float* __restrict__ C, int ldc,
                  int M, int N, int K, int relu)
{
    __shared__ __align__(16) char smem[SMEM_TF];
    const uint32_t smem_base = smem_u32(smem);

    const int tid  = threadIdx.x;
    const int wid  = tid >> 5, lane = tid & 31;
    const int g    = lane >> 2, t = lane & 3;

    const int blockRow = blockIdx.x * 128;
    const int blockCol = blockIdx.y * 128;
    const int warp_m = (wid & 3) * 32;
    const int warp_n = (wid >> 2) * 64;

    const int am0 = tid >> 2;
    const int akc = tid & 3;
    const int bk0 = tid >> 5;
    const int bnc = tid & 31;

    const int NIT = K >> 4;

    float acc[2][8][4];
#pragma unroll
    for (int mt = 0; mt < 2; mt++)
#pragma unroll
        for (int nt = 0; nt < 8; nt++)
#pragma unroll
            for (int i = 0; i < 4; i++) acc[mt][nt][i] = 0.0f;

    auto load_tiles = [&](int it, int stage) {
        const int k0 = it << 4;
        const uint32_t sa = smem_base + stage * STG;
        const uint32_t sb = sa + ASZ;
        {
            int r0 = blockRow + am0;
            int r1 = r0 + 64;
            const char* p0 = (const char*)(A + (size_t)r0 * lda + k0 + akc * 4);
            const char* p1 = (const char*)(A + (size_t)r1 * lda + k0 + akc * 4);
            cp_async16(sa + am0 * (ASTRIDE * 4) + akc * 16, p0, r0 < M ? 16 : 0);
            cp_async16(sa + (am0 + 64) * (ASTRIDE * 4) + akc * 16, p1, r1 < M ? 16 : 0);
        }
        {
            const char* p0 = (const char*)(W + (size_t)(k0 + bk0) * N + blockCol + bnc * 4);
            const char* p1 = (const char*)(W + (size_t)(k0 + bk0 + 8) * N + blockCol + bnc * 4);
            cp_async16(sb + bk0 * (BSTRIDE * 4) + bnc * 16, p0, 16);
            cp_async16(sb + (bk0 + 8) * (BSTRIDE * 4) + bnc * 16, p1, 16);
        }
        CP_ASYNC_COMMIT();
    };

    load_tiles(0, 0);
    int fetch = 1;

    for (int it = 0; it < NIT; it++) {
        CP_ASYNC_WAIT0();
        __syncthreads();
        if (fetch < NIT) { load_tiles(fetch, fetch & 1); fetch++; }

        const float* As = (const float*)(smem + (it & 1) * STG);
        const float* Bs = (const float*)(smem + (it & 1) * STG + ASZ);

#pragma unroll
        for (int ks = 0; ks < 2; ks++) {
            uint32_t a[2][4];
#pragma unroll
            for (int mt = 0; mt < 2; mt++) {
                const int m0 = warp_m + mt * 16 + g;
                const int kk = ks * 8 + t;
                a[mt][0] = tf32_round_bits(As[m0 * ASTRIDE + kk]);
                a[mt][1] = tf32_round_bits(As[(m0 + 8) * ASTRIDE + kk]);
                a[mt][2] = tf32_round_bits(As[m0 * ASTRIDE + kk + 4]);
                a[mt][3] = tf32_round_bits(As[(m0 + 8) * ASTRIDE + kk + 4]);
            }
            uint32_t b[8][2];
#pragma unroll
            for (int nt = 0; nt < 8; nt++) {
                const int n0 = warp_n + nt * 8 + g;
                const int kk = ks * 8 + t;
                b[nt][0] = __float_as_uint(Bs[kk * BSTRIDE + n0]);
                b[nt][1] = __float_as_uint(Bs[(kk + 4) * BSTRIDE + n0]);
            }
#pragma unroll
            for (int mt = 0; mt < 2; mt++)
#pragma unroll
                for (int nt = 0; nt < 8; nt++)
                    mma_tf32(acc[mt][nt][0], acc[mt][nt][1], acc[mt][nt][2], acc[mt][nt][3],
                             a[mt][0], a[mt][1], a[mt][2], a[mt][3],
                             b[nt][0], b[nt][1]);
        }
        __syncthreads();
    }

#pragma unroll
    for (int nt = 0; nt < 8; nt++) {
        const int col = blockCol + warp_n + nt * 8 + 2 * t;
        const float2 bv = *reinterpret_cast<const float2*>(&bias[col]);
#pragma unroll
        for (int mt = 0; mt < 2; mt++) {
#pragma unroll
            for (int half = 0; half < 2; half++) {
                const int row = blockRow + warp_m + mt * 16 + g + half * 8;
                if (row >= M) continue;
                float v0 = acc[mt][nt][half * 2 + 0] + bv.x;
                float v1 = acc[mt][nt][half * 2 + 1] + bv.y;
                if (relu) { v0 = fmaxf(v0, 0.f); v1 = fmaxf(v1, 0.f); }
                *reinterpret_cast<float2*>(C + (size_t)row * ldc + col) = make_float2(v0, v1);
            }
        }
    }
}

// ---------------------------------------------------------------------------
__global__ __launch_bounds__(256, 2)
void gemm_simt(const float* __restrict__ A, int lda,
               const float* __restrict__ W, int ldw,
               const float* __restrict__ bias,
               float* __restrict__ C, int ldc,
               int M, int N, int K, int relu)
{
    int gm = blockIdx.x * 64 + (threadIdx.x >> 2);
    int nq = (threadIdx.x & 3) * 8;
    if (gm >= M) return;
    float acc[8] = {0,0,0,0,0,0,0,0};
    const float* a = A + (size_t)gm * lda;
    for (int k = 0; k < K; k++) {
        float av = a[k];
        const float* wr = W + (size_t)k * ldw + nq;
#pragma unroll
        for (int j = 0; j < 8; j++) acc[j] = fmaf(av, wr[j], acc[j]);
    }
#pragma unroll
    for (int j = 0; j < 8; j++) {
        float v = acc[j] + bias[nq + j];
        if (relu) v = fmaxf(v, 0.0f);
        C[(size_t)gm * ldc + nq + j] = v;
    }
}

__global__ void final_kernel(const float* __restrict__ w,
                             const float* __restrict__ f3w,
                             const float* __restrict__ f3b,
                             float* __restrict__ out, int B)
{
    const int r = blockIdx.x * blockDim.x + threadIdx.x;
    if (r >= B) return;
    float s = 0.0f;
#pragma unroll
    for (int k = 0; k < 32; k++) s = fmaf(w[(size_t)r * 32 + k], f3w[k], s);
    out[r] = s + f3b[0];
}

// ---------------------------------------------------------------------------
extern "C" void kernel_launch(void* const* d_in, const int* in_sizes, int n_in,
                              void* d_out, int out_size)
{
    const float* pairs     = (const float*)d_in[0];
    const int*   idx_pairs = (const int*)  d_in[1];
    const float* aw  = (const float*)d_in[3];
    const float* ab  = (const float*)d_in[4];
    const float* bw  = (const float*)d_in[5];
    const float* bb  = (const float*)d_in[6];
    const float* p1w = (const float*)d_in[7];
    const float* p1b = (const float*)d_in[8];
    const float* p2w = (const float*)d_in[9];
    const float* p2b = (const float*)d_in[10];
    const float* p3w = (const float*)d_in[11];
    const float* p3b = (const float*)d_in[12];
    const float* f1w = (const float*)d_in[13];
    const float* f1b = (const float*)d_in[14];
    const float* f2w = (const float*)d_in[15];
    const float* f2b = (const float*)d_in[16];
    const float* f3w = (const float*)d_in[17];
    const float* f3b = (const float*)d_in[18];
    float* out = (float*)d_out;

    const int P = in_sizes[0] / 160;
    const int B = in_sizes[1];
    const int group = P / B;

    cudaFuncSetAttribute(embed_all,       cudaFuncAttributeMaxDynamicSharedMemorySize, SMEM_EA);
    cudaFuncSetAttribute(tc_gemm_bf16,    cudaFuncAttributeMaxDynamicSharedMemorySize, SMEM_BF3);
    cudaFuncSetAttribute(fused_p2_segsum, cudaFuncAttributeMaxDynamicSharedMemorySize, SMEM_P2);

    __nv_bfloat16 *h384, *h512, *wbf;
    float *part, *hm, *y, *z, *w, *wtf;
    cudaGetSymbolAddress((void**)&h384, g_h384);
    cudaGetSymbolAddress((void**)&h512, g_h512);
    cudaGetSymbolAddress((void**)&part, g_part);
    cudaGetSymbolAddress((void**)&hm,   g_hm);
    cudaGetSymbolAddress((void**)&y,    g_y);
    cudaGetSymbolAddress((void**)&z,    g_z);
    cudaGetSymbolAddress((void**)&w,    g_w);
    cudaGetSymbolAddress((void**)&wbf,  g_wbf);
    cudaGetSymbolAddress((void**)&wtf,  g_wtf);

    __nv_bfloat16* awt = wbf;                    // [128][64]
    __nv_bfloat16* bwt = awt + 128 * 64;         // [128][32]
    __nv_bfloat16* p1t = bwt + 128 * 32;         // [512][384]
    __nv_bfloat16* p2t = p1t + 512 * 384;        // [256][512]
    float* p3r = wtf;                            // [256][1024]
    float* f1r = p3r + 256 * 1024;               // [1024][512]

    wt_bf16<<<(128 * 64  + 255) / 256, 256>>>(aw,  awt, 64, 128);
    wt_bf16<<<(128 * 32  + 255) / 256, 256>>>(bw,  bwt, 32, 128);
    wt_bf16<<<(512 * 384 + 255) / 256, 256>>>(p1w, p1t, 384, 512);
    wt_bf16<<<(256 * 512 + 255) / 256, 256>>>(p2w, p2t, 512, 256);
    round_copy<<<(256 * 1024 / 4 + 255) / 256, 256>>>(p3w, p3r, 256 * 1024 / 4);
    round_copy<<<(1024 * 512 / 4 + 255) / 256, 256>>>(f1w, f1r, 1024 * 512 / 4);
    zero_kernel<<<(2 * B * 256 + 255) / 256, 256>>>(part, 2 * B * 256);

    const int NT = (P + 127) / 128;

    embed_all<<<NT, 256, SMEM_EA>>>(pairs, awt, bwt, ab, bb, h384, P);
    tc_gemm_bf16<<<dim3(NT, 4), 256, SMEM_BF3>>>(h384, 384, p1t, p1b, h512, 512, P, 512, 384);
    fused_p2_segsum<<<NT, 256, SMEM_P2>>>(h512, p2t, p2b, part, P, group, B);
    hm_combine<<<(B * 256 + 255) / 256, 256>>>(part, idx_pairs, hm, B);

    const int BT = (B + 127) / 128;
    tc_gemm_tf32<<<dim3(BT, 8), 256>>>(hm, 256, p3r, p3b, y, 1024, B, 1024, 256, 0);
    tc_gemm_tf32<<<dim3(BT, 4), 256>>>(y, 1024, f1r, f1b, z, 512,  B, 512, 1024, 1);
    gemm_simt<<<(B + 63) / 64, 256>>>(z, 512, f2w, 32, f2b, w, 32, B, 32, 512, 1);
    final_kernel<<<(B + 255) / 256, 256>>>(w, f3w, f3b, out, B);
}

// round 9
// speedup vs baseline: 1.3461x; 1.0320x over previous
#include <cuda_runtime.h>
#include <cuda_bf16.h>
#include <cstdint>

// ===========================================================================
// TGNN R9 — bf16 ldmatrix mma.sync, BK=64 double-buffer everywhere.
//   prep_all       : all weight transforms + partial zeroing, ONE launch
//   embed_all      : fp32 pairs -> (in-reg bf16) -> 3 embed GEMMs -> h384
//   tc_gemm_v2     : generic bf16 GEMM, BK=64, 1 barrier per 64k
//                    (p1, p3, f1 via flags)
//   fused_p2_segsum: p2 BK=64 + deterministic segment sums
//   f2/final SIMT fp32
// ===========================================================================

#define P_MAX  200000
#define B_MAX  2000

__device__ __nv_bfloat16 g_h384[(size_t)P_MAX * 384];
__device__ __nv_bfloat16 g_h512[(size_t)P_MAX * 512];
__device__ float g_part[2 * (size_t)B_MAX * 256];
__device__ __nv_bfloat16 g_hm_bf[(size_t)B_MAX * 256];
__device__ __nv_bfloat16 g_y_bf [(size_t)B_MAX * 1024];
__device__ float g_z   [(size_t)B_MAX * 512];
__device__ float g_w   [(size_t)B_MAX * 32];
__device__ __nv_bfloat16 g_wbf[2 * 1024 * 1024];

// ---------------------------------------------------------------------------
__device__ __forceinline__ uint32_t bf2_bits(float lo, float hi) {
    __nv_bfloat162 p = __float22bfloat162_rn(make_float2(lo, hi));
    return *reinterpret_cast<uint32_t*>(&p);
}
__device__ __forceinline__ void cp_async16(uint32_t smem_addr, const void* gptr, int src_bytes) {
    asm volatile("cp.async.ca.shared.global [%0], [%1], 16, %2;\n"
                 :: "r"(smem_addr), "l"(gptr), "r"(src_bytes));
}
#define CP_ASYNC_COMMIT() asm volatile("cp.async.commit_group;\n" ::: "memory")
#define CP_ASYNC_WAIT0()  asm volatile("cp.async.wait_group 0;\n" ::: "memory")

__device__ __forceinline__ uint32_t smem_u32(const void* p) {
    uint32_t a;
    asm("{ .reg .u64 t; cvta.to.shared.u64 t, %1; cvt.u32.u64 %0, t; }" : "=r"(a) : "l"(p));
    return a;
}
__device__ __forceinline__ void mma_bf16(float& c0, float& c1, float& c2, float& c3,
                                         uint32_t a0, uint32_t a1, uint32_t a2, uint32_t a3,
                                         uint32_t b0, uint32_t b1) {
    asm volatile(
        "mma.sync.aligned.m16n8k16.row.col.f32.bf16.bf16.f32 "
        "{%0,%1,%2,%3}, {%4,%5,%6,%7}, {%8,%9}, {%0,%1,%2,%3};"
        : "+f"(c0), "+f"(c1), "+f"(c2), "+f"(c3)
        : "r"(a0), "r"(a1), "r"(a2), "r"(a3), "r"(b0), "r"(b1));
}
__device__ __forceinline__ void ldsm_x4(uint32_t* r, uint32_t addr) {
    asm volatile("ldmatrix.sync.aligned.m8n8.x4.shared.b16 {%0,%1,%2,%3}, [%4];"
                 : "=r"(r[0]), "=r"(r[1]), "=r"(r[2]), "=r"(r[3]) : "r"(addr));
}

// ---------------------------------------------------------------------------
// Tile block = 128 rows x 32 k bf16; smem row = 64B data + 16B pad (80B).
// ---------------------------------------------------------------------------
#define TILE_B 10240

__device__ __forceinline__ void load_tile(uint32_t dst, const __nv_bfloat16* __restrict__ src,
                                          int ld, int rbase, int rmax, int k0, int tid)
{
#pragma unroll
    for (int h = 0; h < 2; h++) {
        const int chunk = tid + h * 256;
        const int row = chunk >> 2;
        const int ck  = chunk & 3;
        const int gr  = rbase + row;
        const char* p = (const char*)(src + (size_t)gr * ld + k0 + ck * 8);
        cp_async16(dst + row * 80 + ck * 16, p, gr < rmax ? 16 : 0);
    }
}

// ldmatrix k32 block (proven R8 mapping)
__device__ __forceinline__ void mma_block_ldsm(uint32_t Abase, uint32_t Bbase,
                                               float acc[2][8][4],
                                               int lane, int warp_m, int warp_n)
{
    const int l7  = lane & 7;
    const int lb3 = (lane >> 3) & 1;
    const int lb4 = lane >> 4;
#pragma unroll
    for (int ks = 0; ks < 2; ks++) {
        uint32_t a[2][4];
#pragma unroll
        for (int mt = 0; mt < 2; mt++) {
            uint32_t addr = Abase + (uint32_t)(warp_m + mt * 16 + lb3 * 8 + l7) * 80
                          + ks * 32 + lb4 * 16;
            ldsm_x4(a[mt], addr);
        }
        uint32_t b[8][2];
#pragma unroll
        for (int np = 0; np < 4; np++) {
            uint32_t r[4];
            uint32_t addr = Bbase + (uint32_t)(warp_n + np * 16 + lb4 * 8 + l7) * 80
                          + ks * 32 + lb3 * 16;
            ldsm_x4(r, addr);
            b[2 * np][0]     = r[0];
            b[2 * np][1]     = r[1];
            b[2 * np + 1][0] = r[2];
            b[2 * np + 1][1] = r[3];
        }
#pragma unroll
        for (int mt = 0; mt < 2; mt++)
#pragma unroll
            for (int nt = 0; nt < 8; nt++)
                mma_bf16(acc[mt][nt][0], acc[mt][nt][1], acc[mt][nt][2], acc[mt][nt][3],
                         a[mt][0], a[mt][1], a[mt][2], a[mt][3],
                         b[nt][0], b[nt][1]);
    }
}

// ===========================================================================
// embed_all (proven R8): one CTA = 128 rows, three embed slabs. 81920 B smem.
// ===========================================================================
#define SMEM_EA (5 * TILE_B + 3 * TILE_B)

__global__ __launch_bounds__(256)
void embed_all(const float* __restrict__ pairs,
               const __nv_bfloat16* __restrict__ awt,
               const __nv_bfloat16* __restrict__ bwt,
               const float* __restrict__ ab, const float* __restrict__ bb,
               __nv_bfloat16* __restrict__ h384, int P)
{
    extern __shared__ char smem[];
    const uint32_t smem_base = smem_u32(smem);

    const int tid = threadIdx.x;
    const int wid = tid >> 5, lane = tid & 31;
    const int g = lane >> 2, t = lane & 3;
    const int warp_m = (wid & 3) * 32;
    const int warp_n = (wid >> 2) * 64;
    const int blockRow = blockIdx.x * 128;

    load_tile(smem_base + 5 * TILE_B,           awt, 64, 0, 1 << 30, 0,  tid);
    load_tile(smem_base + 5 * TILE_B + TILE_B,  awt, 64, 0, 1 << 30, 32, tid);
    load_tile(smem_base + 7 * TILE_B,           bwt, 32, 0, 1 << 30, 0,  tid);
    CP_ASYNC_COMMIT();

    {
        const int r = tid >> 1;
        const int h = tid & 1;
        const int gr = blockRow + r;
        const bool ok = (gr < P);
        const float* rp = pairs + (size_t)gr * 160 + h * 80;
#pragma unroll
        for (int i = 0; i < 20; i++) {
            float4 v = ok ? *reinterpret_cast<const float4*>(rp + i * 4)
                          : make_float4(0.f, 0.f, 0.f, 0.f);
            const int col = h * 80 + i * 4;
            const int kb = col >> 5, kin = col & 31;
            uint2 pk;
            pk.x = bf2_bits(v.x, v.y);
            pk.y = bf2_bits(v.z, v.w);
            *reinterpret_cast<uint2*>(smem + kb * TILE_B + r * 80 + kin * 2) = pk;
        }
    }
    CP_ASYNC_WAIT0();
    __syncthreads();

    float acc[2][8][4];
#pragma unroll
    for (int c = 0; c < 3; c++) {
        const int nkb = (c < 2) ? 2 : 1;
        const int ab0 = c * 2;
        const uint32_t woff = (c < 2) ? 5 * TILE_B : 7 * TILE_B;
        const float* biasc = (c < 2) ? ab : bb;

#pragma unroll
        for (int mt = 0; mt < 2; mt++)
#pragma unroll
            for (int nt = 0; nt < 8; nt++)
#pragma unroll
                for (int i = 0; i < 4; i++) acc[mt][nt][i] = 0.0f;

        for (int kb = 0; kb < nkb; kb++)
            mma_block_ldsm(smem_base + (ab0 + kb) * TILE_B,
                           smem_base + woff + kb * TILE_B,
                           acc, lane, warp_m, warp_n);

#pragma unroll
        for (int nt = 0; nt < 8; nt++) {
            const int col = warp_n + nt * 8 + 2 * t;
            const float2 bv = *(const float2*)&biasc[col];
#pragma unroll
            for (int mt = 0; mt < 2; mt++)
#pragma unroll
                for (int half = 0; half < 2; half++) {
                    const int row = blockRow + warp_m + mt * 16 + half * 8 + g;
                    if (row >= P) continue;
                    float v0 = fmaxf(acc[mt][nt][half * 2 + 0] + bv.x, 0.f);
                    float v1 = fmaxf(acc[mt][nt][half * 2 + 1] + bv.y, 0.f);
                    *(__nv_bfloat162*)(h384 + (size_t)row * 384 + c * 128 + col) =
                        __float22bfloat162_rn(make_float2(v0, v1));
                }
        }
    }
}

// ===========================================================================
// tc_gemm_v2: C = act(A @ WT^T + bias), BK=64, 2-stage double buffer,
// 1 barrier per 64k. Stage = 4*TILE_B; smem = 8*TILE_B = 81920 -> 2 CTA/SM.
// K % 64 == 0, N tile = 128 per blockIdx.y. Output bf16 or fp32.
// ===========================================================================
#define STAGE64  (4 * TILE_B)
#define SMEM_V2  (2 * STAGE64)

__global__ __launch_bounds__(256)
void tc_gemm_v2(const __nv_bfloat16* __restrict__ A, int lda,
                const __nv_bfloat16* __restrict__ WT,
                const float* __restrict__ bias,
                void* __restrict__ Cv, int ldc,
                int M, int K, int relu, int out_bf16)
{
    extern __shared__ char smem[];
    const uint32_t smem_base = smem_u32(smem);

    const int tid  = threadIdx.x;
    const int wid  = tid >> 5, lane = tid & 31;
    const int g    = lane >> 2, t = lane & 3;

    const int blockRow = blockIdx.x * 128;
    const int blockCol = blockIdx.y * 128;
    const int warp_m = (wid & 3) * 32;
    const int warp_n = (wid >> 2) * 64;

    const int NIT = K >> 6;   // 64-k blocks, assumed >= 2

    float acc[2][8][4];
#pragma unroll
    for (int mt = 0; mt < 2; mt++)
#pragma unroll
        for (int nt = 0; nt < 8; nt++)
#pragma unroll
            for (int i = 0; i < 4; i++) acc[mt][nt][i] = 0.0f;

    auto load_stage = [&](int it) {
        const uint32_t base = smem_base + (it & 1) * STAGE64;
        const int k0 = it * 64;
        load_tile(base,              A,  lda, blockRow, M,       k0,      tid);
        load_tile(base + TILE_B,     A,  lda, blockRow, M,       k0 + 32, tid);
        load_tile(base + 2 * TILE_B, WT, K,   blockCol, 1 << 30, k0,      tid);
        load_tile(base + 3 * TILE_B, WT, K,   blockCol, 1 << 30, k0 + 32, tid);
        CP_ASYNC_COMMIT();
    };

    load_stage(0);

    for (int it = 0; it < NIT; it++) {
        CP_ASYNC_WAIT0();
        __syncthreads();
        if (it + 1 < NIT) load_stage(it + 1);
        const uint32_t base = smem_base + (it & 1) * STAGE64;
        mma_block_ldsm(base,          base + 2 * TILE_B, acc, lane, warp_m, warp_n);
        mma_block_ldsm(base + TILE_B, base + 3 * TILE_B, acc, lane, warp_m, warp_n);
    }

#pragma unroll
    for (int nt = 0; nt < 8; nt++) {
        const int col = blockCol + warp_n + nt * 8 + 2 * t;
        const float2 bv = *reinterpret_cast<const float2*>(&bias[col]);
#pragma unroll
        for (int mt = 0; mt < 2; mt++)
#pragma unroll
            for (int half = 0; half < 2; half++) {
                const int row = blockRow + warp_m + mt * 16 + half * 8 + g;
                if (row >= M) continue;
                float v0 = acc[mt][nt][half * 2 + 0] + bv.x;
                float v1 = acc[mt][nt][half * 2 + 1] + bv.y;
                if (relu) { v0 = fmaxf(v0, 0.f); v1 = fmaxf(v1, 0.f); }
                if (out_bf16) {
                    *(__nv_bfloat162*)((__nv_bfloat16*)Cv + (size_t)row * ldc + col) =
                        __float22bfloat162_rn(make_float2(v0, v1));
                } else {
                    *reinterpret_cast<float2*>((float*)Cv + (size_t)row * ldc + col) =
                        make_float2(v0, v1);
                }
            }
    }
}

// ===========================================================================
// fused_p2_segsum: p2 GEMM (BK=64 double buffer) + deterministic segment
// sums. red tile (66048 B) aliases the pipeline stages (81920 B total smem).
// ===========================================================================
#define REDPAD 129
#define SMEM_P2 (2 * STAGE64)   // 81920 >= 128*129*4

__global__ __launch_bounds__(256)
void fused_p2_segsum(const __nv_bfloat16* __restrict__ h512,
                     const __nv_bfloat16* __restrict__ p2t,
                     const float* __restrict__ p2b,
                     float* __restrict__ part, int P, int group, int Bseg)
{
    extern __shared__ char smem[];
    const uint32_t smem_base = smem_u32(smem);
    float* red = (float*)smem;

    const int tid = threadIdx.x;
    const int wid = tid >> 5, lane = tid & 31;
    const int g = lane >> 2, t = lane & 3;
    const int warp_m = (wid & 3) * 32;
    const int warp_n = (wid >> 2) * 64;
    const int blockRow = blockIdx.x * 128;

    float acc[2][8][4];

    for (int nc = 0; nc < 2; nc++) {
#pragma unroll
        for (int mt = 0; mt < 2; mt++)
#pragma unroll
            for (int nt = 0; nt < 8; nt++)
#pragma unroll
                for (int i = 0; i < 4; i++) acc[mt][nt][i] = 0.0f;

        auto load_stage = [&](int it) {
            const uint32_t base = smem_base + (it & 1) * STAGE64;
            const int k0 = it * 64;
            load_tile(base,              h512, 512, blockRow, P,       k0,      tid);
            load_tile(base + TILE_B,     h512, 512, blockRow, P,       k0 + 32, tid);
            load_tile(base + 2 * TILE_B, p2t,  512, nc * 128, 1 << 30, k0,      tid);
            load_tile(base + 3 * TILE_B, p2t,  512, nc * 128, 1 << 30, k0 + 32, tid);
            CP_ASYNC_COMMIT();
        };

        load_stage(0);
        for (int it = 0; it < 8; it++) {          // K=512 -> 8 blocks of 64
            CP_ASYNC_WAIT0();
            __syncthreads();
            if (it + 1 < 8) load_stage(it + 1);
            const uint32_t base = smem_base + (it & 1) * STAGE64;
            mma_block_ldsm(base,          base + 2 * TILE_B, acc, lane, warp_m, warp_n);
            mma_block_ldsm(base + TILE_B, base + 3 * TILE_B, acc, lane, warp_m, warp_n);
        }
        __syncthreads();   // drain before red aliases the stages

#pragma unroll
        for (int nt = 0; nt < 8; nt++) {
            const int col = warp_n + nt * 8 + 2 * t;
            const float2 bv = *(const float2*)&p2b[nc * 128 + col];
#pragma unroll
            for (int mt = 0; mt < 2; mt++)
#pragma unroll
                for (int half = 0; half < 2; half++) {
                    const int row = warp_m + mt * 16 + half * 8 + g;
                    red[row * REDPAD + col]     = fmaxf(acc[mt][nt][half * 2 + 0] + bv.x, 0.f);
                    red[row * REDPAD + col + 1] = fmaxf(acc[mt][nt][half * 2 + 1] + bv.y, 0.f);
                }
        }
        __syncthreads();

        {
            const int col = tid & 127;
            const int rb  = (tid >> 7) * 64;
            float s = 0.f;
            bool any = false;
            int curseg = 0, nxt = 0;
            for (int r = rb; r < rb + 64; r++) {
                const int grow = blockRow + r;
                if (grow >= P) break;
                if (!any) {
                    curseg = grow / group;
                    nxt = (curseg + 1) * group;
                    any = true;
                } else if (grow >= nxt) {
                    const int slot = blockIdx.x - (curseg * group) / 128;
                    atomicAdd(&part[(size_t)slot * Bseg * 256 + curseg * 256 + nc * 128 + col], s);
                    s = 0.f;
                    curseg++;
                    nxt += group;
                }
                s += red[r * REDPAD + col];
            }
            if (any) {
                const int slot = blockIdx.x - (curseg * group) / 128;
                atomicAdd(&part[(size_t)slot * Bseg * 256 + curseg * 256 + nc * 128 + col], s);
            }
        }
        __syncthreads();
    }
}

// ===========================================================================
// prep_all: all weight transposes/conversions + part zeroing, one launch.
//   segment layout in g_wbf (all [N][K] bf16):
//     awt 128*64 | bwt 128*32 | p1t 512*384 | p2t 256*512 |
//     p3t 1024*256 | f1t 512*1024
// ===========================================================================
#define AWT_SZ  (128 * 64)
#define BWT_SZ  (128 * 32)
#define P1T_SZ  (512 * 384)
#define P2T_SZ  (256 * 512)
#define P3T_SZ  (1024 * 256)
#define F1T_SZ  (512 * 1024)
#define ZERO_SZ (2 * B_MAX * 256)
#define PREP_TOTAL (AWT_SZ + BWT_SZ + P1T_SZ + P2T_SZ + P3T_SZ + F1T_SZ + ZERO_SZ)

__global__ void prep_all(const float* __restrict__ aw,  const float* __restrict__ bw,
                         const float* __restrict__ p1w, const float* __restrict__ p2w,
                         const float* __restrict__ p3w, const float* __restrict__ f1w,
                         __nv_bfloat16* __restrict__ wbf, float* __restrict__ part)
{
    int i = blockIdx.x * blockDim.x + threadIdx.x;
    if (i >= PREP_TOTAL) return;
    int off = 0;
    if (i < off + AWT_SZ) {
        int j = i - off; int n = j / 64, k = j % 64;
        wbf[i] = __float2bfloat16(aw[(size_t)k * 128 + n]); return;
    } off += AWT_SZ;
    if (i < off + BWT_SZ) {
        int j = i - off; int n = j / 32, k = j % 32;
        wbf[i] = __float2bfloat16(bw[(size_t)k * 128 + n]); return;
    } off += BWT_SZ;
    if (i < off + P1T_SZ) {
        int j = i - off; int n = j / 384, k = j % 384;
        wbf[i] = __float2bfloat16(p1w[(size_t)k * 512 + n]); return;
    } off += P1T_SZ;
    if (i < off + P2T_SZ) {
        int j = i - off; int n = j / 512, k = j % 512;
        wbf[i] = __float2bfloat16(p2w[(size_t)k * 256 + n]); return;
    } off += P2T_SZ;
    if (i < off + P3T_SZ) {
        int j = i - off; int n = j / 256, k = j % 256;
        wbf[i] = __float2bfloat16(p3w[(size_t)k * 1024 + n]); return;
    } off += P3T_SZ;
    if (i < off + F1T_SZ) {
        int j = i - off; int n = j / 1024, k = j % 1024;
        wbf[i] = __float2bfloat16(f1w[(size_t)k * 512 + n]); return;
    } off += F1T_SZ;
    part[i - off] = 0.0f;
}

// ---------------------------------------------------------------------------
__global__ void hm_combine(const float* __restrict__ part, const int* __restrict__ idx,
                           __nv_bfloat16* __restrict__ hm, int Bseg)
{
    int i = blockIdx.x * blockDim.x + threadIdx.x;
    if (i >= Bseg * 256) return;
    int s = i >> 8;
    hm[i] = __float2bfloat16((part[i] + part[(size_t)Bseg * 256 + i]) / (float)idx[s]);
}

// ---------------------------------------------------------------------------
// small SIMT layers (f2: z fp32 -> w fp32; final)
// ---------------------------------------------------------------------------
__global__ __launch_bounds__(256, 2)
void gemm_simt(const float* __restrict__ A, int lda,
               const float* __restrict__ W, int ldw,
               const float* __restrict__ bias,
               float* __restrict__ C, int ldc,
               int M, int N, int K, int relu)
{
    int gm = blockIdx.x * 64 + (threadIdx.x >> 2);
    int nq = (threadIdx.x & 3) * 8;
    if (gm >= M) return;
    float acc[8] = {0,0,0,0,0,0,0,0};
    const float* a = A + (size_t)gm * lda;
    for (int k = 0; k < K; k++) {
        float av = a[k];
        const float* wr = W + (size_t)k * ldw + nq;
#pragma unroll
        for (int j = 0; j < 8; j++) acc[j] = fmaf(av, wr[j], acc[j]);
    }
#pragma unroll
    for (int j = 0; j < 8; j++) {
        float v = acc[j] + bias[nq + j];
        if (relu) v = fmaxf(v, 0.0f);
        C[(size_t)gm * ldc + nq + j] = v;
    }
}

__global__ void final_kernel(const float* __restrict__ w,
                             const float* __restrict__ f3w,
                             const float* __restrict__ f3b,
                             float* __restrict__ out, int B)
{
    const int r = blockIdx.x * blockDim.x + threadIdx.x;
    if (r >= B) return;
    float s = 0.0f;
#pragma unroll
    for (int k = 0; k < 32; k++) s = fmaf(w[(size_t)r * 32 + k], f3w[k], s);
    out[r] = s + f3b[0];
}

// ---------------------------------------------------------------------------
extern "C" void kernel_launch(void* const* d_in, const int* in_sizes, int n_in,
                              void* d_out, int out_size)
{
    const float* pairs     = (const float*)d_in[0];
    const int*   idx_pairs = (const int*)  d_in[1];
    const float* aw  = (const float*)d_in[3];
    const float* ab  = (const float*)d_in[4];
    const float* bw  = (const float*)d_in[5];
    const float* bb  = (const float*)d_in[6];
    const float* p1w = (const float*)d_in[7];
    const float* p1b = (const float*)d_in[8];
    const float* p2w = (const float*)d_in[9];
    const float* p2b = (const float*)d_in[10];
    const float* p3w = (const float*)d_in[11];
    const float* p3b = (const float*)d_in[12];
    const float* f1w = (const float*)d_in[13];
    const float* f1b = (const float*)d_in[14];
    const float* f2w = (const float*)d_in[15];
    const float* f2b = (const float*)d_in[16];
    const float* f3w = (const float*)d_in[17];
    const float* f3b = (const float*)d_in[18];
    float* out = (float*)d_out;

    const int P = in_sizes[0] / 160;
    const int B = in_sizes[1];
    const int group = P / B;

    cudaFuncSetAttribute(embed_all,       cudaFuncAttributeMaxDynamicSharedMemorySize, SMEM_EA);
    cudaFuncSetAttribute(tc_gemm_v2,      cudaFuncAttributeMaxDynamicSharedMemorySize, SMEM_V2);
    cudaFuncSetAttribute(fused_p2_segsum, cudaFuncAttributeMaxDynamicSharedMemorySize, SMEM_P2);

    __nv_bfloat16 *h384, *h512, *hm_bf, *y_bf, *wbf;
    float *part, *z, *w;
    cudaGetSymbolAddress((void**)&h384,  g_h384);
    cudaGetSymbolAddress((void**)&h512,  g_h512);
    cudaGetSymbolAddress((void**)&part,  g_part);
    cudaGetSymbolAddress((void**)&hm_bf, g_hm_bf);
    cudaGetSymbolAddress((void**)&y_bf,  g_y_bf);
    cudaGetSymbolAddress((void**)&z,     g_z);
    cudaGetSymbolAddress((void**)&w,     g_w);
    cudaGetSymbolAddress((void**)&wbf,   g_wbf);

    __nv_bfloat16* awt = wbf;
    __nv_bfloat16* bwt = awt + AWT_SZ;
    __nv_bfloat16* p1t = bwt + BWT_SZ;
    __nv_bfloat16* p2t = p1t + P1T_SZ;
    __nv_bfloat16* p3t = p2t + P2T_SZ;
    __nv_bfloat16* f1t = p3t + P3T_SZ;

    prep_all<<<(PREP_TOTAL + 255) / 256, 256>>>(aw, bw, p1w, p2w, p3w, f1w, wbf, part);

    const int NT = (P + 127) / 128;

    embed_all<<<NT, 256, SMEM_EA>>>(pairs, awt, bwt, ab, bb, h384, P);
    tc_gemm_v2<<<dim3(NT, 4), 256, SMEM_V2>>>(h384, 384, p1t, p1b, h512, 512, P, 384, 1, 1);
    fused_p2_segsum<<<NT, 256, SMEM_P2>>>(h512, p2t, p2b, part, P, group, B);
    hm_combine<<<(B * 256 + 255) / 256, 256>>>(part, idx_pairs, hm_bf, B);

    const int BT = (B + 127) / 128;
    tc_gemm_v2<<<dim3(BT, 8), 256, SMEM_V2>>>(hm_bf, 256, p3t, p3b, y_bf, 1024, B, 256, 0, 1);
    tc_gemm_v2<<<dim3(BT, 4), 256, SMEM_V2>>>(y_bf, 1024, f1t, f1b, z, 512, B, 1024, 1, 0);
    gemm_simt<<<(B + 63) / 64, 256>>>(z, 512, f2w, 32, f2b, w, 32, B, 32, 512, 1);
    final_kernel<<<(B + 255) / 256, 256>>>(w, f3w, f3b, out, B);
}